// round 13
// baseline (speedup 1.0000x reference)
#include <cuda_runtime.h>
#include <cuda_fp16.h>
#include <cstdint>

#define NNODES 10000
#define F_IN   256
#define HID    512
#define C_OUT  128
#define NEDGES 320000
#define KCAT   512            // K for both fused GEMMs

// ---------------------------------------------------------------------------
// Scratch (allocation-free rule: __device__ globals)
// g_deg: zero-initialized at load; re-zeroed by build_rowptr after each
// consume -> every invocation (incl. graph replays) sees zeros.
// Precision scheme: A operands single fp16 (rel err 2^-11, random sign ->
// random-walk ~2^-12 on K=512 dots); B operands exact fp16 hi+lo split.
// D = Ah*Bh + Ah*Bl  (2 MMA products instead of 3).
// ---------------------------------------------------------------------------
__device__ __align__(1024) float  g_P  [NNODES * C_OUT];       // h @ W2l fp32
__device__ __align__(1024) __half g_A1 [NNODES * KCAT];        // [agg1|x] fp16
__device__ __align__(1024) __half g_H  [NNODES * KCAT];        // h fp16
__device__ __align__(1024) __half g_B1h[HID * KCAT];           // [W1l;W1r]^T hi [512][512]
__device__ __align__(1024) __half g_B1l[HID * KCAT];           // lo residue
__device__ __align__(1024) __half g_B2h[(2 * C_OUT) * KCAT];   // [W2l|W2r]^T hi [256][512]
__device__ __align__(1024) __half g_B2l[(2 * C_OUT) * KCAT];
__device__ int g_src[NEDGES];
__device__ int g_dst[NEDGES];
__device__ int g_seq[NEDGES];
__device__ int g_deg[NNODES];
__device__ int g_rowptr[NNODES + 1];
__device__ int g_csr[NEDGES];

// ---------------------------------------------------------------------------
// PTX helpers (plain sm_80+ PTX; NO sm_103a-only features — harness targets sm_103)
// ---------------------------------------------------------------------------
__device__ __forceinline__ uint32_t smem_u32(const void* p) {
    uint32_t a;
    asm("{ .reg .u64 t; cvta.to.shared.u64 t, %1; cvt.u32.u64 %0, t; }"
        : "=r"(a) : "l"(p));
    return a;
}
#define CP_ASYNC16(dst, src, sz) \
    asm volatile("cp.async.cg.shared.global [%0], [%1], 16, %2;" \
                 :: "r"(dst), "l"(src), "r"(sz) : "memory")
#define CP_COMMIT() asm volatile("cp.async.commit_group;" ::: "memory")
#define CP_WAIT0()  asm volatile("cp.async.wait_group 0;" ::: "memory")
#define LDSM_X4(r0, r1, r2, r3, addr) \
    asm volatile("ldmatrix.sync.aligned.m8n8.x4.shared.b16 {%0,%1,%2,%3}, [%4];" \
                 : "=r"(r0), "=r"(r1), "=r"(r2), "=r"(r3) : "r"(addr))

__device__ __forceinline__ void mma16816(float c[4],
                                         uint32_t a0, uint32_t a1, uint32_t a2, uint32_t a3,
                                         uint32_t b0, uint32_t b1) {
    asm volatile(
        "mma.sync.aligned.m16n8k16.row.col.f32.f16.f16.f32 "
        "{%0,%1,%2,%3}, {%4,%5,%6,%7}, {%8,%9}, {%0,%1,%2,%3};"
        : "+f"(c[0]), "+f"(c[1]), "+f"(c[2]), "+f"(c[3])
        : "r"(a0), "r"(a1), "r"(a2), "r"(a3), "r"(b0), "r"(b1));
}

__device__ __forceinline__ uint32_t swz(uint32_t off) {   // SW128-style XOR
    return off ^ ((off >> 3) & 0x70);
}

// fp32 -> fp16 hi/lo exact split (residue ~2^-22), packed as half2 words.
__device__ __forceinline__ void split2h(float a, float b, uint32_t& h2o, uint32_t& l2o) {
    __half2 hv, lv;
    hv.x = __float2half(a);
    hv.y = __float2half(b);
    lv.x = __float2half(a - __half2float(hv.x));
    lv.y = __float2half(b - __half2float(hv.y));
    h2o = *reinterpret_cast<uint32_t*>(&hv);
    l2o = *reinterpret_cast<uint32_t*>(&lv);
}

// fp32 pair -> packed fp16x2 (single precision level)
__device__ __forceinline__ uint32_t pack2h(float a, float b) {
    __half2 hv;
    hv.x = __float2half(a);
    hv.y = __float2half(b);
    return *reinterpret_cast<uint32_t*>(&hv);
}

__device__ __forceinline__ int clampi(long long v, int hi) {
    int r = (int)v;
    if (v < 0) r = 0;
    if (v >= hi) r = hi - 1;
    return r;
}

// ---------------------------------------------------------------------------
// Front kernel: grid-partitioned independent work running concurrently.
//   blocks [0, eb):      edge decode (2 edges/thread) + degree hist + seq
//   blocks [eb, eb+96):  weight transpose + fp16 split (64x64 smem tiles)
//   blocks [eb+96, ...): x -> fp16 into A1[:, 256:512]
// ---------------------------------------------------------------------------
__global__ void convert_and_prep(const void* __restrict__ ei,
                                 const float* __restrict__ x,
                                 const float* __restrict__ W1l, const float* __restrict__ W1r,
                                 const float* __restrict__ W2l, const float* __restrict__ W2r,
                                 int eb, int E, int M) {
    const int b = blockIdx.x;
    const int tid = threadIdx.x;

    if (b < eb) {
        __shared__ int s_any;
        if (tid == 0) s_any = 0;
        __syncthreads();
        const int* p32 = (const int*)ei;
        int n_check = (2 * E < 2048) ? 2 * E : 2048;
        int any = 0;
        for (int i = 2 * tid + 1; i < n_check; i += 512) any |= p32[i];
        if (any) atomicOr(&s_any, 1);
        __syncthreads();
        const int is32 = s_any;

        int e0 = (b * 256 + tid) * 2;
        if (e0 + 1 < E) {
            long long s0, s1, d0, d1;
            if (is32) {
                int2 sp = *(const int2*)(p32 + e0);
                int2 dp = *(const int2*)(p32 + E + e0);
                s0 = sp.x; s1 = sp.y; d0 = dp.x; d1 = dp.y;
            } else {
                const long long* p64 = (const long long*)ei;
                longlong2 sp = *(const longlong2*)(p64 + e0);
                longlong2 dp = *(const longlong2*)(p64 + E + e0);
                s0 = sp.x; s1 = sp.y; d0 = dp.x; d1 = dp.y;
            }
            int si0 = clampi(s0, NNODES), si1 = clampi(s1, NNODES);
            int di0 = clampi(d0, NNODES), di1 = clampi(d1, NNODES);
            *(int2*)(g_src + e0) = make_int2(si0, si1);
            *(int2*)(g_dst + e0) = make_int2(di0, di1);
            int q0 = atomicAdd(&g_deg[di0], 1);
            int q1 = atomicAdd(&g_deg[di1], 1);
            *(int2*)(g_seq + e0) = make_int2(q0, q1);
        }
        return;
    }

    if (b < eb + 96) {
        const int wb = b - eb;
        __shared__ float tile[64][65];
        const float* W;
        __half *Dh, *Dl;
        int ldw, roff, coff, nt, kt;
        if (wb < 64) {                 // layer-1 weights -> g_B1 [512][512]
            nt = (wb & 7) * 64; kt = (wb >> 3) * 64;
            if (kt < 256) { W = W1l; roff = kt; } else { W = W1r; roff = kt - 256; }
            ldw = 512; coff = nt;
            Dh = g_B1h; Dl = g_B1l;
        } else {                       // layer-2 weights -> g_B2 [256][512]
            int t = wb - 64;
            nt = (t & 3) * 64; kt = (t >> 2) * 64;
            if (nt < 128) { W = W2l; coff = nt; } else { W = W2r; coff = nt - 128; }
            ldw = 128; roff = kt;
            Dh = g_B2h; Dl = g_B2l;
        }
#pragma unroll
        for (int pass = 0; pass < 16; ++pass) {
            int r = pass * 4 + (tid >> 6);
            int c = tid & 63;
            tile[c][r] = W[(size_t)(roff + r) * ldw + coff + c];
        }
        __syncthreads();
#pragma unroll
        for (int pass = 0; pass < 8; ++pass) {
            int n0 = pass * 8 + (tid >> 5);
            int k0 = (tid & 31) * 2;
            uint32_t h2, l2;
            split2h(tile[n0][k0], tile[n0][k0 + 1], h2, l2);
            size_t off = (size_t)(nt + n0) * KCAT + kt + k0;
            *(uint32_t*)(Dh + off) = h2;
            *(uint32_t*)(Dl + off) = l2;
        }
        return;
    }

    // ---- x -> fp16 into A1[:, 256:512] ----
    int p = (b - eb - 96) * 256 + tid;
    if (p < M * 128) {
        int m = p >> 7;
        int c2 = (p & 127) * 2;
        *(uint32_t*)(g_A1 + (size_t)m * KCAT + 256 + c2) =
            pack2h(x[m * 256 + c2], x[m * 256 + c2 + 1]);
    }
}

// ---------------------------------------------------------------------------
// Exclusive scan of g_deg -> g_rowptr (coalesced via smem staging).
// Re-zeroes g_deg for the next invocation.
// ---------------------------------------------------------------------------
__global__ void build_rowptr() {
    __shared__ int sdeg[NNODES];      // 40 KB
    __shared__ int wsum[32];
    const int t = threadIdx.x;
    const int lane = t & 31, w = t >> 5;

    for (int i = t; i < NNODES; i += 1024) {
        sdeg[i] = g_deg[i];
        g_deg[i] = 0;
    }
    __syncthreads();

    const int base = t * 16;
    int local[16];
    int s = 0;
#pragma unroll
    for (int i = 0; i < 16; ++i) {
        int idx = base + i;
        int v = (idx < NNODES) ? sdeg[idx] : 0;
        local[i] = s; s += v;
    }
    int inc = s;
#pragma unroll
    for (int o = 1; o < 32; o <<= 1) {
        int v = __shfl_up_sync(0xffffffffu, inc, o);
        if (lane >= o) inc += v;
    }
    if (lane == 31) wsum[w] = inc;
    __syncthreads();
    if (w == 0) {
        int v2 = wsum[lane];
#pragma unroll
        for (int o = 1; o < 32; o <<= 1) {
            int u = __shfl_up_sync(0xffffffffu, v2, o);
            if (lane >= o) v2 += u;
        }
        wsum[lane] = v2;
    }
    __syncthreads();
    int excl = inc - s + (w ? wsum[w - 1] : 0);
#pragma unroll
    for (int i = 0; i < 16; ++i) {
        int idx = base + i;
        if (idx < NNODES) sdeg[idx] = excl + local[i];
    }
    __syncthreads();
    for (int i = t; i < NNODES; i += 1024) g_rowptr[i] = sdeg[i];
    if (t == 1023) g_rowptr[NNODES] = wsum[31];
}

// Atomic-free CSR fill, 4 edges/thread.
__global__ void fill_csr(int E) {
    int e0 = (blockIdx.x * blockDim.x + threadIdx.x) * 4;
    if (e0 + 3 < E) {
        int4 d = *(const int4*)(g_dst + e0);
        int4 q = *(const int4*)(g_seq + e0);
        int4 s = *(const int4*)(g_src + e0);
        int r0 = g_rowptr[d.x];
        int r1 = g_rowptr[d.y];
        int r2 = g_rowptr[d.z];
        int r3 = g_rowptr[d.w];
        g_csr[r0 + q.x] = s.x;
        g_csr[r1 + q.y] = s.y;
        g_csr[r2 + q.z] = s.z;
        g_csr[r3 + q.w] = s.w;
    } else {
        for (int e = e0; e < E; ++e)
            g_csr[g_rowptr[g_dst[e]] + g_seq[e]] = g_src[e];
    }
}

// ---------------------------------------------------------------------------
// Layer-1 gather fused with fp16 convert: A1[:, 0:256] = fp16(segsum(x)).
// ---------------------------------------------------------------------------
__global__ void gather_splitA(const float* __restrict__ X, int Nn) {
    int node = (blockIdx.x * blockDim.x + threadIdx.x) >> 5;
    if (node >= Nn) return;
    int lane = threadIdx.x & 31;
    int r0 = g_rowptr[node];
    int r1 = g_rowptr[node + 1];

    float4 acc[2];
    acc[0] = make_float4(0.f, 0.f, 0.f, 0.f);
    acc[1] = make_float4(0.f, 0.f, 0.f, 0.f);

    int e = r0;
    for (; e + 1 < r1; e += 2) {
        const float4* p0 = (const float4*)(X + (size_t)g_csr[e] * F_IN);
        const float4* p1 = (const float4*)(X + (size_t)g_csr[e + 1] * F_IN);
#pragma unroll
        for (int j = 0; j < 2; ++j) {
            float4 a = p0[lane + 32 * j];
            float4 b = p1[lane + 32 * j];
            acc[j].x += a.x + b.x;
            acc[j].y += a.y + b.y;
            acc[j].z += a.z + b.z;
            acc[j].w += a.w + b.w;
        }
    }
    if (e < r1) {
        const float4* p0 = (const float4*)(X + (size_t)g_csr[e] * F_IN);
#pragma unroll
        for (int j = 0; j < 2; ++j) {
            float4 a = p0[lane + 32 * j];
            acc[j].x += a.x; acc[j].y += a.y;
            acc[j].z += a.z; acc[j].w += a.w;
        }
    }

#pragma unroll
    for (int j = 0; j < 2; ++j) {
        int col = (lane + 32 * j) * 4;
        *(uint2*)(g_A1 + (size_t)node * KCAT + col) =
            make_uint2(pack2h(acc[j].x, acc[j].y), pack2h(acc[j].z, acc[j].w));
    }
}

// P-gather: out[node] += segsum(P), F=128, fp32.
__global__ void gather_P(const float* __restrict__ X, float* __restrict__ OUT, int Nn) {
    int node = (blockIdx.x * blockDim.x + threadIdx.x) >> 5;
    if (node >= Nn) return;
    int lane = threadIdx.x & 31;
    int r0 = g_rowptr[node];
    int r1 = g_rowptr[node + 1];

    float4 acc = ((const float4*)(OUT + (size_t)node * C_OUT))[lane];
    int e = r0;
    for (; e + 1 < r1; e += 2) {
        float4 a = ((const float4*)(X + (size_t)g_csr[e] * C_OUT))[lane];
        float4 b = ((const float4*)(X + (size_t)g_csr[e + 1] * C_OUT))[lane];
        acc.x += a.x + b.x; acc.y += a.y + b.y;
        acc.z += a.z + b.z; acc.w += a.w + b.w;
    }
    if (e < r1) {
        float4 a = ((const float4*)(X + (size_t)g_csr[e] * C_OUT))[lane];
        acc.x += a.x; acc.y += a.y; acc.z += a.z; acc.w += a.w;
    }
    ((float4*)(OUT + (size_t)node * C_OUT))[lane] = acc;
}

// ---------------------------------------------------------------------------
// HMMA fp16 2-product GEMM.  C = A @ (Bh + Bl).  Tile 128x64, BK=64, 8 warps.
// Stage: A 16KB + Bh 8KB + Bl 8KB = 32KB; double buffered = 64KB; 2 CTAs/SM.
// MODE 0 (layer1): C = relu(A@B + bias) -> fp16 H [M][512]
// MODE 1 (layer2): cols <128 -> P (no bias); cols >=128 -> OUT (+b2). fp32.
// ---------------------------------------------------------------------------
#define STAGE_BYTES 32768
#define GSMEM (2 * STAGE_BYTES)

template <int MODE>
__global__ void __launch_bounds__(256, 2)
gemm_mma(const __half* __restrict__ A,
         const __half* __restrict__ Bh, const __half* __restrict__ Bl,
         const float* __restrict__ bias,       // MODE0: b1
         __half* __restrict__ H,
         float* __restrict__ P, float* __restrict__ OUT,
         const float* __restrict__ b2, int M) {
    extern __shared__ char smem_raw[];
    const uint32_t sb = smem_u32(smem_raw);
    const int tid  = threadIdx.x;
    const int lane = tid & 31;
    const int w    = tid >> 5;
    const int wm   = w & 3;          // 4 m-blocks of 32
    const int wn   = w >> 2;         // 2 n-blocks of 32
    const int bm   = blockIdx.y * 128;
    const int bn   = blockIdx.x * 64;
    constexpr int T = KCAT / 64;     // 8

    float acc[2][4][4];
#pragma unroll
    for (int i = 0; i < 2; ++i)
#pragma unroll
        for (int j = 0; j < 4; ++j)
#pragma unroll
            for (int c = 0; c < 4; ++c) acc[i][j][c] = 0.f;

    auto load_tile = [&](int t, int s) {
        const int kk = t * 64;
        const uint32_t b0 = sb + s * STAGE_BYTES;
        const uint32_t dA = b0, dBh = b0 + 16384, dBl = b0 + 24576;
#pragma unroll
        for (int i = 0; i < 4; ++i) {                 // A: 1024 chunks (128 rows x 8)
            int idx = tid + i * 256;
            int row = idx >> 3, c = idx & 7;
            int gm = bm + row;
            uint32_t off = swz(row * 128 + c * 16);
            int sz = (gm < M) ? 16 : 0;
            CP_ASYNC16(dA + off, (const char*)(A + (size_t)gm * KCAT + kk + c * 8), sz);
        }
#pragma unroll
        for (int i = 0; i < 2; ++i) {                 // B: 512 chunks (64 n-rows x 8)
            int idx = tid + i * 256;
            int row = idx >> 3, c = idx & 7;
            int gn = bn + row;
            uint32_t off = swz(row * 128 + c * 16);
            CP_ASYNC16(dBh + off, (const char*)(Bh + (size_t)gn * KCAT + kk + c * 8), 16);
            CP_ASYNC16(dBl + off, (const char*)(Bl + (size_t)gn * KCAT + kk + c * 8), 16);
        }
    };

    const int lr16 = lane & 15;
    const int lc8  = (lane >> 4) * 8;

    auto compute = [&](int s) {
        const uint32_t b0 = sb + s * STAGE_BYTES;
        const uint32_t aA = b0, bH = b0 + 16384, bL = b0 + 24576;
#pragma unroll
        for (int ks = 0; ks < 4; ++ks) {
            const int k0 = ks * 16;
            uint32_t ah[2][4];
#pragma unroll
            for (int i = 0; i < 2; ++i) {
                uint32_t off = swz((uint32_t)((wm * 32 + i * 16 + lr16) * 128 + (k0 + lc8) * 2));
                LDSM_X4(ah[i][0], ah[i][1], ah[i][2], ah[i][3], aA + off);
            }
            uint32_t bh[4][2], bl[4][2];
#pragma unroll
            for (int jp = 0; jp < 2; ++jp) {
                uint32_t off = swz((uint32_t)((wn * 32 + jp * 16 + lr16) * 128 + (k0 + lc8) * 2));
                uint32_t q0, q1, q2, q3;
                LDSM_X4(q0, q1, q2, q3, bH + off);
                bh[2 * jp][0] = q0; bh[2 * jp][1] = q2;
                bh[2 * jp + 1][0] = q1; bh[2 * jp + 1][1] = q3;
                LDSM_X4(q0, q1, q2, q3, bL + off);
                bl[2 * jp][0] = q0; bl[2 * jp][1] = q2;
                bl[2 * jp + 1][0] = q1; bl[2 * jp + 1][1] = q3;
            }
#pragma unroll
            for (int i = 0; i < 2; ++i)
#pragma unroll
                for (int j = 0; j < 4; ++j) {
                    mma16816(acc[i][j], ah[i][0], ah[i][1], ah[i][2], ah[i][3],
                             bh[j][0], bh[j][1]);
                    mma16816(acc[i][j], ah[i][0], ah[i][1], ah[i][2], ah[i][3],
                             bl[j][0], bl[j][1]);
                }
        }
    };

    load_tile(0, 0);
    CP_COMMIT();
    for (int t = 0; t < T; ++t) {
        const int s = t & 1;
        CP_WAIT0();
        __syncthreads();
        if (t + 1 < T) { load_tile(t + 1, s ^ 1); CP_COMMIT(); }
        compute(s);
        __syncthreads();
    }

    // ---- epilogue ----
#pragma unroll
    for (int i = 0; i < 2; ++i) {
        const int m0 = bm + wm * 32 + i * 16 + (lane >> 2);
#pragma unroll
        for (int j = 0; j < 4; ++j) {
            const int n = bn + wn * 32 + j * 8 + (lane & 3) * 2;
            if (MODE == 0) {
                float2 bb = *(const float2*)(bias + n);
                float v0 = fmaxf(acc[i][j][0] + bb.x, 0.f);
                float v1 = fmaxf(acc[i][j][1] + bb.y, 0.f);
                float v2 = fmaxf(acc[i][j][2] + bb.x, 0.f);
                float v3 = fmaxf(acc[i][j][3] + bb.y, 0.f);
                if (m0 < M)
                    *(uint32_t*)(H + (size_t)m0 * KCAT + n) = pack2h(v0, v1);
                if (m0 + 8 < M)
                    *(uint32_t*)(H + (size_t)(m0 + 8) * KCAT + n) = pack2h(v2, v3);
            } else {
                float* Csel = (n < 128) ? P : OUT;
                const int cn = (n < 128) ? n : (n - 128);
                float bx = 0.f, by = 0.f;
                if (n >= 128) { float2 bb = *(const float2*)(b2 + cn); bx = bb.x; by = bb.y; }
                if (m0 < M)
                    *(float2*)(Csel + (size_t)m0 * C_OUT + cn) =
                        make_float2(acc[i][j][0] + bx, acc[i][j][1] + by);
                if (m0 + 8 < M)
                    *(float2*)(Csel + (size_t)(m0 + 8) * C_OUT + cn) =
                        make_float2(acc[i][j][2] + bx, acc[i][j][3] + by);
            }
        }
    }
}

// ---------------------------------------------------------------------------
extern "C" void kernel_launch(void* const* d_in, const int* in_sizes, int n_in,
                              void* d_out, int out_size) {
    const float* x   = (const float*)d_in[0];
    const void*  ei  = d_in[1];
    const float* W1l = (const float*)d_in[2];
    const float* b1  = (const float*)d_in[3];
    const float* W1r = (const float*)d_in[4];
    const float* W2l = (const float*)d_in[5];
    const float* b2  = (const float*)d_in[6];
    const float* W2r = (const float*)d_in[7];
    float*       out = (float*)d_out;

    const int M = in_sizes[0] / F_IN;    // 10000
    const int E = in_sizes[1] / 2;       // 320000

    float* P;
    __half *A1, *H, *B1h, *B1l, *B2h, *B2l;
    cudaGetSymbolAddress((void**)&P,   g_P);
    cudaGetSymbolAddress((void**)&A1,  g_A1);
    cudaGetSymbolAddress((void**)&H,   g_H);
    cudaGetSymbolAddress((void**)&B1h, g_B1h);
    cudaGetSymbolAddress((void**)&B1l, g_B1l);
    cudaGetSymbolAddress((void**)&B2h, g_B2h);
    cudaGetSymbolAddress((void**)&B2l, g_B2l);

    static int smem_set = 0;
    if (!smem_set) {
        cudaFuncSetAttribute(gemm_mma<0>, cudaFuncAttributeMaxDynamicSharedMemorySize, GSMEM);
        cudaFuncSetAttribute(gemm_mma<1>, cudaFuncAttributeMaxDynamicSharedMemorySize, GSMEM);
        smem_set = 1;
    }

    // ---- front kernel: edge decode + hist concurrent with weight/x prep ----
    const int eb = (E + 511) / 512;
    const int xb = (M * 128 + 255) / 256;
    convert_and_prep<<<eb + 96 + xb, 256>>>(ei, x, W1l, W1r, W2l, W2r, eb, E, M);

    // ---- CSR: scan (+deg reset) then atomic-free fill ----
    build_rowptr<<<1, 1024>>>();
    fill_csr<<<(E / 4 + 255) / 256 + 1, 256>>>(E);

    // ---- Layer 1: A1[:,0:256] = fp16(segsum(x));
    //      h(fp16) = relu(A1 @ [W1l;W1r] + b1) ----
    gather_splitA<<<(M * 32 + 255) / 256, 256>>>(x, M);
    {
        dim3 grid(HID / 64, (M + 127) / 128);   // (8, 79)
        gemm_mma<0><<<grid, 256, GSMEM>>>(A1, B1h, B1l, b1,
                                          H, nullptr, nullptr, nullptr, M);
    }

    // ---- Layer 2 (linearity reorder): [P|out] = h @ [W2l|W2r] (+b2 on out);
    //      out += segsum(P) ----
    {
        dim3 grid(2 * C_OUT / 64, (M + 127) / 128);  // (4, 79)
        gemm_mma<1><<<grid, 256, GSMEM>>>(H, B2h, B2l, nullptr,
                                          nullptr, P, out, b2, M);
    }
    gather_P<<<(M * 32 + 255) / 256, 256>>>(P, out, M);
}

// round 15
// speedup vs baseline: 1.2180x; 1.2180x over previous
#include <cuda_runtime.h>
#include <cuda_bf16.h>
#include <cuda_fp16.h>
#include <cstdint>

#define NNODES 10000
#define F_IN   256
#define HID    512
#define C_OUT  128
#define NEDGES 320000
#define KCAT   512            // K for both fused GEMMs

// ---------------------------------------------------------------------------
// Scratch (allocation-free rule: __device__ globals)
// g_deg: zero-initialized at load; re-zeroed by build_rowptr after each
// consume -> every invocation (incl. graph replays) sees zeros.
// ---------------------------------------------------------------------------
__device__ __align__(1024) float g_P   [NNODES * C_OUT];         // h @ W2l fp32
__device__ __align__(1024) __half g_Xh [NNODES * F_IN];          // x fp16 copy (gather source)
__device__ __align__(1024) __nv_bfloat16 g_A1h[NNODES * KCAT];   // [agg1|x] hi
__device__ __align__(1024) __nv_bfloat16 g_A1l[NNODES * KCAT];   // [agg1|x] lo
__device__ __align__(1024) __nv_bfloat16 g_Hh [NNODES * KCAT];   // h hi
__device__ __align__(1024) __nv_bfloat16 g_Hl [NNODES * KCAT];   // h lo
__device__ __align__(1024) __nv_bfloat16 g_B1h[HID * KCAT];      // [W1l;W1r]^T hi [512][512]
__device__ __align__(1024) __nv_bfloat16 g_B1l[HID * KCAT];
__device__ __align__(1024) __nv_bfloat16 g_B2h[(2 * C_OUT) * KCAT]; // [W2l|W2r]^T hi [256][512]
__device__ __align__(1024) __nv_bfloat16 g_B2l[(2 * C_OUT) * KCAT];
__device__ int g_src[NEDGES];
__device__ int g_dst[NEDGES];
__device__ int g_seq[NEDGES];       // per-dest sequence number (from hist atomic)
__device__ int g_deg[NNODES];
__device__ int g_rowptr[NNODES + 1];
__device__ int g_csr[NEDGES];

// ---------------------------------------------------------------------------
// PTX helpers (plain sm_80+ PTX; NO sm_103a-only features — harness targets sm_103)
// ---------------------------------------------------------------------------
__device__ __forceinline__ uint32_t smem_u32(const void* p) {
    uint32_t a;
    asm("{ .reg .u64 t; cvta.to.shared.u64 t, %1; cvt.u32.u64 %0, t; }"
        : "=r"(a) : "l"(p));
    return a;
}
#define CP_ASYNC16(dst, src, sz) \
    asm volatile("cp.async.cg.shared.global [%0], [%1], 16, %2;" \
                 :: "r"(dst), "l"(src), "r"(sz) : "memory")
#define CP_COMMIT() asm volatile("cp.async.commit_group;" ::: "memory")
#define CP_WAIT0()  asm volatile("cp.async.wait_group 0;" ::: "memory")
#define LDSM_X4(r0, r1, r2, r3, addr) \
    asm volatile("ldmatrix.sync.aligned.m8n8.x4.shared.b16 {%0,%1,%2,%3}, [%4];" \
                 : "=r"(r0), "=r"(r1), "=r"(r2), "=r"(r3) : "r"(addr))

__device__ __forceinline__ void mma16816(float c[4],
                                         uint32_t a0, uint32_t a1, uint32_t a2, uint32_t a3,
                                         uint32_t b0, uint32_t b1) {
    asm volatile(
        "mma.sync.aligned.m16n8k16.row.col.f32.bf16.bf16.f32 "
        "{%0,%1,%2,%3}, {%4,%5,%6,%7}, {%8,%9}, {%0,%1,%2,%3};"
        : "+f"(c[0]), "+f"(c[1]), "+f"(c[2]), "+f"(c[3])
        : "r"(a0), "r"(a1), "r"(a2), "r"(a3), "r"(b0), "r"(b1));
}

__device__ __forceinline__ uint32_t swz(uint32_t off) {   // SW128-style XOR
    return off ^ ((off >> 3) & 0x70);
}

__device__ __forceinline__ void split2(float a, float b, uint32_t& h2o, uint32_t& l2o) {
    __nv_bfloat162 hv, lv;
    hv.x = __float2bfloat16(a);
    hv.y = __float2bfloat16(b);
    lv.x = __float2bfloat16(a - __bfloat162float(hv.x));
    lv.y = __float2bfloat16(b - __bfloat162float(hv.y));
    h2o = *reinterpret_cast<uint32_t*>(&hv);
    l2o = *reinterpret_cast<uint32_t*>(&lv);
}

__device__ __forceinline__ uint32_t pack2h(float a, float b) {
    __half2 hv;
    hv.x = __float2half(a);
    hv.y = __float2half(b);
    return *reinterpret_cast<uint32_t*>(&hv);
}

__device__ __forceinline__ int clampi(long long v, int hi) {
    int r = (int)v;
    if (v < 0) r = 0;
    if (v >= hi) r = hi - 1;
    return r;
}

// ---------------------------------------------------------------------------
// Front kernel: grid-partitioned independent work running concurrently.
//   blocks [0, eb):      edge decode (2 edges/thread) + degree hist + seq
//   blocks [eb, eb+96):  weight transpose + bf16 split (64x64 smem tiles)
//   blocks [eb+96, ...): x -> bf16 split into A1[:, 256:512] AND fp16 copy g_Xh
// ---------------------------------------------------------------------------
__global__ void convert_and_prep(const void* __restrict__ ei,
                                 const float* __restrict__ x,
                                 const float* __restrict__ W1l, const float* __restrict__ W1r,
                                 const float* __restrict__ W2l, const float* __restrict__ W2r,
                                 int eb, int E, int M) {
    const int b = blockIdx.x;
    const int tid = threadIdx.x;

    if (b < eb) {
        __shared__ int s_any;
        if (tid == 0) s_any = 0;
        __syncthreads();
        const int* p32 = (const int*)ei;
        int n_check = (2 * E < 2048) ? 2 * E : 2048;
        int any = 0;
        for (int i = 2 * tid + 1; i < n_check; i += 512) any |= p32[i];
        if (any) atomicOr(&s_any, 1);
        __syncthreads();
        const int is32 = s_any;

        int e0 = (b * 256 + tid) * 2;
        if (e0 + 1 < E) {
            long long s0, s1, d0, d1;
            if (is32) {
                int2 sp = *(const int2*)(p32 + e0);
                int2 dp = *(const int2*)(p32 + E + e0);
                s0 = sp.x; s1 = sp.y; d0 = dp.x; d1 = dp.y;
            } else {
                const long long* p64 = (const long long*)ei;
                longlong2 sp = *(const longlong2*)(p64 + e0);
                longlong2 dp = *(const longlong2*)(p64 + E + e0);
                s0 = sp.x; s1 = sp.y; d0 = dp.x; d1 = dp.y;
            }
            int si0 = clampi(s0, NNODES), si1 = clampi(s1, NNODES);
            int di0 = clampi(d0, NNODES), di1 = clampi(d1, NNODES);
            *(int2*)(g_src + e0) = make_int2(si0, si1);
            *(int2*)(g_dst + e0) = make_int2(di0, di1);
            int q0 = atomicAdd(&g_deg[di0], 1);
            int q1 = atomicAdd(&g_deg[di1], 1);
            *(int2*)(g_seq + e0) = make_int2(q0, q1);
        }
        return;
    }

    if (b < eb + 96) {
        const int wb = b - eb;
        __shared__ float tile[64][65];
        const float* W;
        __nv_bfloat16 *Dh, *Dl;
        int ldw, roff, coff, nt, kt;
        if (wb < 64) {                 // layer-1 weights -> g_B1 [512][512]
            nt = (wb & 7) * 64; kt = (wb >> 3) * 64;
            if (kt < 256) { W = W1l; roff = kt; } else { W = W1r; roff = kt - 256; }
            ldw = 512; coff = nt;
            Dh = g_B1h; Dl = g_B1l;
        } else {                       // layer-2 weights -> g_B2 [256][512]
            int t = wb - 64;
            nt = (t & 3) * 64; kt = (t >> 2) * 64;
            if (nt < 128) { W = W2l; coff = nt; } else { W = W2r; coff = nt - 128; }
            ldw = 128; roff = kt;
            Dh = g_B2h; Dl = g_B2l;
        }
#pragma unroll
        for (int pass = 0; pass < 16; ++pass) {
            int r = pass * 4 + (tid >> 6);
            int c = tid & 63;
            tile[c][r] = W[(size_t)(roff + r) * ldw + coff + c];
        }
        __syncthreads();
#pragma unroll
        for (int pass = 0; pass < 8; ++pass) {
            int n0 = pass * 8 + (tid >> 5);
            int k0 = (tid & 31) * 2;
            uint32_t h2, l2;
            split2(tile[n0][k0], tile[n0][k0 + 1], h2, l2);
            size_t off = (size_t)(nt + n0) * KCAT + kt + k0;
            *(uint32_t*)(Dh + off) = h2;
            *(uint32_t*)(Dl + off) = l2;
        }
        return;
    }

    // ---- x: bf16 split into A1[:, 256:512] + fp16 copy into g_Xh ----
    int p = (b - eb - 96) * 256 + tid;
    if (p < M * 128) {
        int m = p >> 7;
        int c2 = (p & 127) * 2;
        float a  = x[m * 256 + c2];
        float bb = x[m * 256 + c2 + 1];
        uint32_t h2, l2;
        split2(a, bb, h2, l2);
        *(uint32_t*)(g_A1h + (size_t)m * KCAT + 256 + c2) = h2;
        *(uint32_t*)(g_A1l + (size_t)m * KCAT + 256 + c2) = l2;
        *(uint32_t*)(g_Xh + (size_t)m * F_IN + c2) = pack2h(a, bb);
    }
}

// ---------------------------------------------------------------------------
// Exclusive scan of g_deg -> g_rowptr (coalesced via smem staging).
// Re-zeroes g_deg for the next invocation.
// ---------------------------------------------------------------------------
__global__ void build_rowptr() {
    __shared__ int sdeg[NNODES];      // 40 KB
    __shared__ int wsum[32];
    const int t = threadIdx.x;
    const int lane = t & 31, w = t >> 5;

    for (int i = t; i < NNODES; i += 1024) {
        sdeg[i] = g_deg[i];
        g_deg[i] = 0;
    }
    __syncthreads();

    const int base = t * 16;
    int local[16];
    int s = 0;
#pragma unroll
    for (int i = 0; i < 16; ++i) {
        int idx = base + i;
        int v = (idx < NNODES) ? sdeg[idx] : 0;
        local[i] = s; s += v;
    }
    int inc = s;
#pragma unroll
    for (int o = 1; o < 32; o <<= 1) {
        int v = __shfl_up_sync(0xffffffffu, inc, o);
        if (lane >= o) inc += v;
    }
    if (lane == 31) wsum[w] = inc;
    __syncthreads();
    if (w == 0) {
        int v2 = wsum[lane];
#pragma unroll
        for (int o = 1; o < 32; o <<= 1) {
            int u = __shfl_up_sync(0xffffffffu, v2, o);
            if (lane >= o) v2 += u;
        }
        wsum[lane] = v2;
    }
    __syncthreads();
    int excl = inc - s + (w ? wsum[w - 1] : 0);
#pragma unroll
    for (int i = 0; i < 16; ++i) {
        int idx = base + i;
        if (idx < NNODES) sdeg[idx] = excl + local[i];
    }
    __syncthreads();
    for (int i = t; i < NNODES; i += 1024) g_rowptr[i] = sdeg[i];
    if (t == 1023) g_rowptr[NNODES] = wsum[31];
}

// Atomic-free CSR fill, 4 edges/thread.
__global__ void fill_csr(int E) {
    int e0 = (blockIdx.x * blockDim.x + threadIdx.x) * 4;
    if (e0 + 3 < E) {
        int4 d = *(const int4*)(g_dst + e0);
        int4 q = *(const int4*)(g_seq + e0);
        int4 s = *(const int4*)(g_src + e0);
        int r0 = g_rowptr[d.x];
        int r1 = g_rowptr[d.y];
        int r2 = g_rowptr[d.z];
        int r3 = g_rowptr[d.w];
        g_csr[r0 + q.x] = s.x;
        g_csr[r1 + q.y] = s.y;
        g_csr[r2 + q.z] = s.z;
        g_csr[r3 + q.w] = s.w;
    } else {
        for (int e = e0; e < E; ++e)
            g_csr[g_rowptr[g_dst[e]] + g_seq[e]] = g_src[e];
    }
}

// ---------------------------------------------------------------------------
// Layer-1 gather from fp16 x (half the L2 traffic of fp32), fp32 accumulate,
// bf16 hi/lo split into A1[:, 0:256]. Lane owns 8 contiguous cols (one uint4
// load per edge, fully coalesced).
// ---------------------------------------------------------------------------
__global__ void gather_splitA(int Nn) {
    int node = (blockIdx.x * blockDim.x + threadIdx.x) >> 5;
    if (node >= Nn) return;
    int lane = threadIdx.x & 31;
    int r0 = g_rowptr[node];
    int r1 = g_rowptr[node + 1];

    float acc[8];
#pragma unroll
    for (int i = 0; i < 8; ++i) acc[i] = 0.f;

    auto addrow = [&](const uint4 v) {
#pragma unroll
        for (int q = 0; q < 4; ++q) {
            uint32_t word = (q == 0) ? v.x : (q == 1) ? v.y : (q == 2) ? v.z : v.w;
            __half2 h2 = *reinterpret_cast<__half2*>(&word);
            float2 f = __half22float2(h2);
            acc[2 * q]     += f.x;
            acc[2 * q + 1] += f.y;
        }
    };

    int e = r0;
    for (; e + 1 < r1; e += 2) {
        uint4 v0 = ((const uint4*)(g_Xh + (size_t)g_csr[e]     * F_IN))[lane];
        uint4 v1 = ((const uint4*)(g_Xh + (size_t)g_csr[e + 1] * F_IN))[lane];
        addrow(v0);
        addrow(v1);
    }
    if (e < r1) {
        uint4 v0 = ((const uint4*)(g_Xh + (size_t)g_csr[e] * F_IN))[lane];
        addrow(v0);
    }

    // split + store: lane owns cols [lane*8, lane*8+8) of A1[:, 0:256)
    uint32_t h[4], l[4];
#pragma unroll
    for (int q = 0; q < 4; ++q)
        split2(acc[2 * q], acc[2 * q + 1], h[q], l[q]);
    size_t off = (size_t)node * KCAT + lane * 8;
    *(uint4*)(g_A1h + off) = make_uint4(h[0], h[1], h[2], h[3]);
    *(uint4*)(g_A1l + off) = make_uint4(l[0], l[1], l[2], l[3]);
}

// P-gather: out[node] += segsum(P), F=128, fp32.
__global__ void gather_P(const float* __restrict__ X, float* __restrict__ OUT, int Nn) {
    int node = (blockIdx.x * blockDim.x + threadIdx.x) >> 5;
    if (node >= Nn) return;
    int lane = threadIdx.x & 31;
    int r0 = g_rowptr[node];
    int r1 = g_rowptr[node + 1];

    float4 acc = ((const float4*)(OUT + (size_t)node * C_OUT))[lane];
    int e = r0;
    for (; e + 1 < r1; e += 2) {
        float4 a = ((const float4*)(X + (size_t)g_csr[e] * C_OUT))[lane];
        float4 b = ((const float4*)(X + (size_t)g_csr[e + 1] * C_OUT))[lane];
        acc.x += a.x + b.x; acc.y += a.y + b.y;
        acc.z += a.z + b.z; acc.w += a.w + b.w;
    }
    if (e < r1) {
        float4 a = ((const float4*)(X + (size_t)g_csr[e] * C_OUT))[lane];
        acc.x += a.x; acc.y += a.y; acc.z += a.z; acc.w += a.w;
    }
    ((float4*)(OUT + (size_t)node * C_OUT))[lane] = acc;
}

// ---------------------------------------------------------------------------
// HMMA bf16-split GEMM (unchanged from R12).  Tile 128x64, BK=64, 8 warps.
// MODE 0 (layer1): C = relu(A@B + bias); write split bf16 to Hh/Hl [M][512]
// MODE 1 (layer2): cols <128 -> P (no bias); cols >=128 -> OUT (+b2).
// ---------------------------------------------------------------------------
#define STAGE_BYTES 49152
#define GSMEM (2 * STAGE_BYTES)   // Ah16K, Al16K, Bh8K, Bl8K per stage

template <int MODE>
__global__ void __launch_bounds__(256, 2)
gemm_mma(const __nv_bfloat16* __restrict__ Ah, const __nv_bfloat16* __restrict__ Al,
         const __nv_bfloat16* __restrict__ Bh, const __nv_bfloat16* __restrict__ Bl,
         const float* __restrict__ bias,       // MODE0: b1
         __nv_bfloat16* __restrict__ Hh, __nv_bfloat16* __restrict__ Hl,
         float* __restrict__ P, float* __restrict__ OUT,
         const float* __restrict__ b2, int M) {
    extern __shared__ char smem_raw[];
    const uint32_t sb = smem_u32(smem_raw);
    const int tid  = threadIdx.x;
    const int lane = tid & 31;
    const int w    = tid >> 5;
    const int wm   = w & 3;          // 4 m-blocks of 32
    const int wn   = w >> 2;         // 2 n-blocks of 32
    const int bm   = blockIdx.y * 128;
    const int bn   = blockIdx.x * 64;
    constexpr int T = KCAT / 64;     // 8

    float acc[2][4][4];
#pragma unroll
    for (int i = 0; i < 2; ++i)
#pragma unroll
        for (int j = 0; j < 4; ++j)
#pragma unroll
            for (int c = 0; c < 4; ++c) acc[i][j][c] = 0.f;

    auto load_tile = [&](int t, int s) {
        const int kk = t * 64;
        const uint32_t b0 = sb + s * STAGE_BYTES;
        const uint32_t dAh = b0, dAl = b0 + 16384, dBh = b0 + 32768, dBl = b0 + 40960;
#pragma unroll
        for (int i = 0; i < 4; ++i) {                 // A: 1024 chunks (128 rows x 8)
            int idx = tid + i * 256;
            int row = idx >> 3, c = idx & 7;
            int gm = bm + row;
            uint32_t off = swz(row * 128 + c * 16);
            int sz = (gm < M) ? 16 : 0;
            const char* pa = (const char*)(Ah + (size_t)gm * KCAT + kk + c * 8);
            const char* pl = (const char*)(Al + (size_t)gm * KCAT + kk + c * 8);
            CP_ASYNC16(dAh + off, pa, sz);
            CP_ASYNC16(dAl + off, pl, sz);
        }
#pragma unroll
        for (int i = 0; i < 2; ++i) {                 // B: 512 chunks (64 n-rows x 8)
            int idx = tid + i * 256;
            int row = idx >> 3, c = idx & 7;
            int gn = bn + row;
            uint32_t off = swz(row * 128 + c * 16);
            const char* pb = (const char*)(Bh + (size_t)gn * KCAT + kk + c * 8);
            const char* pl = (const char*)(Bl + (size_t)gn * KCAT + kk + c * 8);
            CP_ASYNC16(dBh + off, pb, 16);
            CP_ASYNC16(dBl + off, pl, 16);
        }
    };

    const int lr16 = lane & 15;
    const int lc8  = (lane >> 4) * 8;

    auto compute = [&](int s) {
        const uint32_t b0 = sb + s * STAGE_BYTES;
        const uint32_t aH = b0, aL = b0 + 16384, bH = b0 + 32768, bL = b0 + 40960;
#pragma unroll
        for (int ks = 0; ks < 4; ++ks) {
            const int k0 = ks * 16;
            uint32_t ah[2][4], al[2][4];
#pragma unroll
            for (int i = 0; i < 2; ++i) {
                uint32_t off = swz((uint32_t)((wm * 32 + i * 16 + lr16) * 128 + (k0 + lc8) * 2));
                LDSM_X4(ah[i][0], ah[i][1], ah[i][2], ah[i][3], aH + off);
                LDSM_X4(al[i][0], al[i][1], al[i][2], al[i][3], aL + off);
            }
            uint32_t bh[4][2], bl[4][2];
#pragma unroll
            for (int jp = 0; jp < 2; ++jp) {
                uint32_t off = swz((uint32_t)((wn * 32 + jp * 16 + lr16) * 128 + (k0 + lc8) * 2));
                uint32_t q0, q1, q2, q3;
                LDSM_X4(q0, q1, q2, q3, bH + off);
                bh[2 * jp][0] = q0; bh[2 * jp][1] = q2;
                bh[2 * jp + 1][0] = q1; bh[2 * jp + 1][1] = q3;
                LDSM_X4(q0, q1, q2, q3, bL + off);
                bl[2 * jp][0] = q0; bl[2 * jp][1] = q2;
                bl[2 * jp + 1][0] = q1; bl[2 * jp + 1][1] = q3;
            }
#pragma unroll
            for (int i = 0; i < 2; ++i)
#pragma unroll
                for (int j = 0; j < 4; ++j) {
                    mma16816(acc[i][j], ah[i][0], ah[i][1], ah[i][2], ah[i][3],
                             bh[j][0], bh[j][1]);
                    mma16816(acc[i][j], ah[i][0], ah[i][1], ah[i][2], ah[i][3],
                             bl[j][0], bl[j][1]);
                    mma16816(acc[i][j], al[i][0], al[i][1], al[i][2], al[i][3],
                             bh[j][0], bh[j][1]);
                }
        }
    };

    load_tile(0, 0);
    CP_COMMIT();
    for (int t = 0; t < T; ++t) {
        const int s = t & 1;
        CP_WAIT0();
        __syncthreads();
        if (t + 1 < T) { load_tile(t + 1, s ^ 1); CP_COMMIT(); }
        compute(s);
        __syncthreads();
    }

    // ---- epilogue ----
#pragma unroll
    for (int i = 0; i < 2; ++i) {
        const int m0 = bm + wm * 32 + i * 16 + (lane >> 2);
#pragma unroll
        for (int j = 0; j < 4; ++j) {
            const int n = bn + wn * 32 + j * 8 + (lane & 3) * 2;
            if (MODE == 0) {
                float2 bb = *(const float2*)(bias + n);
                float v0 = fmaxf(acc[i][j][0] + bb.x, 0.f);
                float v1 = fmaxf(acc[i][j][1] + bb.y, 0.f);
                float v2 = fmaxf(acc[i][j][2] + bb.x, 0.f);
                float v3 = fmaxf(acc[i][j][3] + bb.y, 0.f);
                uint32_t h2, l2;
                if (m0 < M) {
                    split2(v0, v1, h2, l2);
                    *(uint32_t*)(Hh + (size_t)m0 * KCAT + n) = h2;
                    *(uint32_t*)(Hl + (size_t)m0 * KCAT + n) = l2;
                }
                if (m0 + 8 < M) {
                    split2(v2, v3, h2, l2);
                    *(uint32_t*)(Hh + (size_t)(m0 + 8) * KCAT + n) = h2;
                    *(uint32_t*)(Hl + (size_t)(m0 + 8) * KCAT + n) = l2;
                }
            } else {
                float* Csel = (n < 128) ? P : OUT;
                const int cn = (n < 128) ? n : (n - 128);
                float bx = 0.f, by = 0.f;
                if (n >= 128) { float2 bb = *(const float2*)(b2 + cn); bx = bb.x; by = bb.y; }
                if (m0 < M)
                    *(float2*)(Csel + (size_t)m0 * C_OUT + cn) =
                        make_float2(acc[i][j][0] + bx, acc[i][j][1] + by);
                if (m0 + 8 < M)
                    *(float2*)(Csel + (size_t)(m0 + 8) * C_OUT + cn) =
                        make_float2(acc[i][j][2] + bx, acc[i][j][3] + by);
            }
        }
    }
}

// ---------------------------------------------------------------------------
extern "C" void kernel_launch(void* const* d_in, const int* in_sizes, int n_in,
                              void* d_out, int out_size) {
    const float* x   = (const float*)d_in[0];
    const void*  ei  = d_in[1];
    const float* W1l = (const float*)d_in[2];
    const float* b1  = (const float*)d_in[3];
    const float* W1r = (const float*)d_in[4];
    const float* W2l = (const float*)d_in[5];
    const float* b2  = (const float*)d_in[6];
    const float* W2r = (const float*)d_in[7];
    float*       out = (float*)d_out;

    const int M = in_sizes[0] / F_IN;    // 10000
    const int E = in_sizes[1] / 2;       // 320000

    float* P;
    __nv_bfloat16 *A1h, *A1l, *Hh, *Hl, *B1h, *B1l, *B2h, *B2l;
    cudaGetSymbolAddress((void**)&P,   g_P);
    cudaGetSymbolAddress((void**)&A1h, g_A1h);
    cudaGetSymbolAddress((void**)&A1l, g_A1l);
    cudaGetSymbolAddress((void**)&Hh,  g_Hh);
    cudaGetSymbolAddress((void**)&Hl,  g_Hl);
    cudaGetSymbolAddress((void**)&B1h, g_B1h);
    cudaGetSymbolAddress((void**)&B1l, g_B1l);
    cudaGetSymbolAddress((void**)&B2h, g_B2h);
    cudaGetSymbolAddress((void**)&B2l, g_B2l);

    static int smem_set = 0;
    if (!smem_set) {
        cudaFuncSetAttribute(gemm_mma<0>, cudaFuncAttributeMaxDynamicSharedMemorySize, GSMEM);
        cudaFuncSetAttribute(gemm_mma<1>, cudaFuncAttributeMaxDynamicSharedMemorySize, GSMEM);
        smem_set = 1;
    }

    // ---- front kernel: edge decode + hist concurrent with weight/x prep ----
    const int eb = (E + 511) / 512;
    const int xb = (M * 128 + 255) / 256;
    convert_and_prep<<<eb + 96 + xb, 256>>>(ei, x, W1l, W1r, W2l, W2r, eb, E, M);

    // ---- CSR: scan (+deg reset) then atomic-free fill ----
    build_rowptr<<<1, 1024>>>();
    fill_csr<<<(E / 4 + 255) / 256 + 1, 256>>>(E);

    // ---- Layer 1: A1[:,0:256] = split(segsum(fp16 x)) (half gather traffic);
    //      h(split) = relu(A1 @ [W1l;W1r] + b1) ----
    gather_splitA<<<(M * 32 + 255) / 256, 256>>>(M);
    {
        dim3 grid(HID / 64, (M + 127) / 128);   // (8, 79)
        gemm_mma<0><<<grid, 256, GSMEM>>>(A1h, A1l, B1h, B1l, b1,
                                          Hh, Hl, nullptr, nullptr, nullptr, M);
    }

    // ---- Layer 2 (linearity reorder): [P|out] = h @ [W2l|W2r] (+b2 on out);
    //      out += segsum(P) ----
    {
        dim3 grid(2 * C_OUT / 64, (M + 127) / 128);  // (4, 79)
        gemm_mma<1><<<grid, 256, GSMEM>>>(Hh, Hl, B2h, B2l, nullptr,
                                          nullptr, nullptr, P, out, b2, M);
    }
    gather_P<<<(M * 32 + 255) / 256, 256>>>(P, out, M);
}

// round 16
// speedup vs baseline: 1.5908x; 1.3060x over previous
#include <cuda_runtime.h>
#include <cuda_fp16.h>
#include <cstdint>

#define NNODES 10000
#define F_IN   256
#define HID    512
#define C_OUT  128
#define NEDGES 320000
#define KCAT   512            // K for both fused GEMMs

// ---------------------------------------------------------------------------
// Scratch (allocation-free rule: __device__ globals)
// g_deg: zero-initialized at load; re-zeroed by build_rowptr after each
// consume -> every invocation (incl. graph replays) sees zeros.
// Precision: A operands single fp16 (2^-11 random-sign rounding); B operands
// exact fp16 hi+lo split (residue 2^-22). D = A*Bh + A*Bl (2 MMA products).
// ---------------------------------------------------------------------------
__device__ __align__(1024) __half g_P  [NNODES * C_OUT];       // h @ W2l fp16
__device__ __align__(1024) __half g_A1 [NNODES * KCAT];        // [agg1|x] fp16 (cols 256:512 = fp16 x, also the gather source)
__device__ __align__(1024) __half g_H  [NNODES * KCAT];        // h fp16
__device__ __align__(1024) __half g_B1h[HID * KCAT];           // [W1l;W1r]^T hi [512][512]
__device__ __align__(1024) __half g_B1l[HID * KCAT];
__device__ __align__(1024) __half g_B2h[(2 * C_OUT) * KCAT];   // [W2l|W2r]^T hi [256][512]
__device__ __align__(1024) __half g_B2l[(2 * C_OUT) * KCAT];
__device__ int g_src[NEDGES];
__device__ int g_dst[NEDGES];
__device__ int g_seq[NEDGES];
__device__ int g_deg[NNODES];
__device__ int g_rowptr[NNODES + 1];
__device__ int g_csr[NEDGES];

// ---------------------------------------------------------------------------
// PTX helpers (plain sm_80+ PTX; NO sm_103a-only features — harness targets sm_103)
// ---------------------------------------------------------------------------
__device__ __forceinline__ uint32_t smem_u32(const void* p) {
    uint32_t a;
    asm("{ .reg .u64 t; cvta.to.shared.u64 t, %1; cvt.u32.u64 %0, t; }"
        : "=r"(a) : "l"(p));
    return a;
}
#define CP_ASYNC16(dst, src, sz) \
    asm volatile("cp.async.cg.shared.global [%0], [%1], 16, %2;" \
                 :: "r"(dst), "l"(src), "r"(sz) : "memory")
#define CP_COMMIT() asm volatile("cp.async.commit_group;" ::: "memory")
#define CP_WAIT0()  asm volatile("cp.async.wait_group 0;" ::: "memory")
#define LDSM_X4(r0, r1, r2, r3, addr) \
    asm volatile("ldmatrix.sync.aligned.m8n8.x4.shared.b16 {%0,%1,%2,%3}, [%4];" \
                 : "=r"(r0), "=r"(r1), "=r"(r2), "=r"(r3) : "r"(addr))

__device__ __forceinline__ void mma16816(float c[4],
                                         uint32_t a0, uint32_t a1, uint32_t a2, uint32_t a3,
                                         uint32_t b0, uint32_t b1) {
    asm volatile(
        "mma.sync.aligned.m16n8k16.row.col.f32.f16.f16.f32 "
        "{%0,%1,%2,%3}, {%4,%5,%6,%7}, {%8,%9}, {%0,%1,%2,%3};"
        : "+f"(c[0]), "+f"(c[1]), "+f"(c[2]), "+f"(c[3])
        : "r"(a0), "r"(a1), "r"(a2), "r"(a3), "r"(b0), "r"(b1));
}

__device__ __forceinline__ uint32_t swz(uint32_t off) {   // SW128-style XOR
    return off ^ ((off >> 3) & 0x70);
}

// fp32 -> fp16 hi/lo exact split (residue ~2^-22), packed as half2 words.
__device__ __forceinline__ void split2h(float a, float b, uint32_t& h2o, uint32_t& l2o) {
    __half2 hv, lv;
    hv.x = __float2half(a);
    hv.y = __float2half(b);
    lv.x = __float2half(a - __half2float(hv.x));
    lv.y = __float2half(b - __half2float(hv.y));
    h2o = *reinterpret_cast<uint32_t*>(&hv);
    l2o = *reinterpret_cast<uint32_t*>(&lv);
}

__device__ __forceinline__ uint32_t pack2h(float a, float b) {
    __half2 hv;
    hv.x = __float2half(a);
    hv.y = __float2half(b);
    return *reinterpret_cast<uint32_t*>(&hv);
}

__device__ __forceinline__ int clampi(long long v, int hi) {
    int r = (int)v;
    if (v < 0) r = 0;
    if (v >= hi) r = hi - 1;
    return r;
}

// ---------------------------------------------------------------------------
// Front kernel: grid-partitioned independent work running concurrently.
//   blocks [0, eb):      edge decode (2 edges/thread) + degree hist + seq
//   blocks [eb, eb+96):  weight transpose + fp16 split (64x64 smem tiles)
//   blocks [eb+96, ...): x -> fp16 into A1[:, 256:512] (doubles as gather src)
// ---------------------------------------------------------------------------
__global__ void convert_and_prep(const void* __restrict__ ei,
                                 const float* __restrict__ x,
                                 const float* __restrict__ W1l, const float* __restrict__ W1r,
                                 const float* __restrict__ W2l, const float* __restrict__ W2r,
                                 int eb, int E, int M) {
    const int b = blockIdx.x;
    const int tid = threadIdx.x;

    if (b < eb) {
        __shared__ int s_any;
        if (tid == 0) s_any = 0;
        __syncthreads();
        const int* p32 = (const int*)ei;
        int n_check = (2 * E < 2048) ? 2 * E : 2048;
        int any = 0;
        for (int i = 2 * tid + 1; i < n_check; i += 512) any |= p32[i];
        if (any) atomicOr(&s_any, 1);
        __syncthreads();
        const int is32 = s_any;

        int e0 = (b * 256 + tid) * 2;
        if (e0 + 1 < E) {
            long long s0, s1, d0, d1;
            if (is32) {
                int2 sp = *(const int2*)(p32 + e0);
                int2 dp = *(const int2*)(p32 + E + e0);
                s0 = sp.x; s1 = sp.y; d0 = dp.x; d1 = dp.y;
            } else {
                const long long* p64 = (const long long*)ei;
                longlong2 sp = *(const longlong2*)(p64 + e0);
                longlong2 dp = *(const longlong2*)(p64 + E + e0);
                s0 = sp.x; s1 = sp.y; d0 = dp.x; d1 = dp.y;
            }
            int si0 = clampi(s0, NNODES), si1 = clampi(s1, NNODES);
            int di0 = clampi(d0, NNODES), di1 = clampi(d1, NNODES);
            *(int2*)(g_src + e0) = make_int2(si0, si1);
            *(int2*)(g_dst + e0) = make_int2(di0, di1);
            int q0 = atomicAdd(&g_deg[di0], 1);
            int q1 = atomicAdd(&g_deg[di1], 1);
            *(int2*)(g_seq + e0) = make_int2(q0, q1);
        }
        return;
    }

    if (b < eb + 96) {
        const int wb = b - eb;
        __shared__ float tile[64][65];
        const float* W;
        __half *Dh, *Dl;
        int ldw, roff, coff, nt, kt;
        if (wb < 64) {                 // layer-1 weights -> g_B1 [512][512]
            nt = (wb & 7) * 64; kt = (wb >> 3) * 64;
            if (kt < 256) { W = W1l; roff = kt; } else { W = W1r; roff = kt - 256; }
            ldw = 512; coff = nt;
            Dh = g_B1h; Dl = g_B1l;
        } else {                       // layer-2 weights -> g_B2 [256][512]
            int t = wb - 64;
            nt = (t & 3) * 64; kt = (t >> 2) * 64;
            if (nt < 128) { W = W2l; coff = nt; } else { W = W2r; coff = nt - 128; }
            ldw = 128; roff = kt;
            Dh = g_B2h; Dl = g_B2l;
        }
#pragma unroll
        for (int pass = 0; pass < 16; ++pass) {
            int r = pass * 4 + (tid >> 6);
            int c = tid & 63;
            tile[c][r] = W[(size_t)(roff + r) * ldw + coff + c];
        }
        __syncthreads();
#pragma unroll
        for (int pass = 0; pass < 8; ++pass) {
            int n0 = pass * 8 + (tid >> 5);
            int k0 = (tid & 31) * 2;
            uint32_t h2, l2;
            split2h(tile[n0][k0], tile[n0][k0 + 1], h2, l2);
            size_t off = (size_t)(nt + n0) * KCAT + kt + k0;
            *(uint32_t*)(Dh + off) = h2;
            *(uint32_t*)(Dl + off) = l2;
        }
        return;
    }

    // ---- x -> fp16 into A1[:, 256:512] ----
    int p = (b - eb - 96) * 256 + tid;
    if (p < M * 128) {
        int m = p >> 7;
        int c2 = (p & 127) * 2;
        *(uint32_t*)(g_A1 + (size_t)m * KCAT + 256 + c2) =
            pack2h(x[m * 256 + c2], x[m * 256 + c2 + 1]);
    }
}

// ---------------------------------------------------------------------------
// Exclusive scan of g_deg -> g_rowptr (coalesced via smem staging).
// Re-zeroes g_deg for the next invocation.
// ---------------------------------------------------------------------------
__global__ void build_rowptr() {
    __shared__ int sdeg[NNODES];      // 40 KB
    __shared__ int wsum[32];
    const int t = threadIdx.x;
    const int lane = t & 31, w = t >> 5;

    for (int i = t; i < NNODES; i += 1024) {
        sdeg[i] = g_deg[i];
        g_deg[i] = 0;
    }
    __syncthreads();

    const int base = t * 16;
    int local[16];
    int s = 0;
#pragma unroll
    for (int i = 0; i < 16; ++i) {
        int idx = base + i;
        int v = (idx < NNODES) ? sdeg[idx] : 0;
        local[i] = s; s += v;
    }
    int inc = s;
#pragma unroll
    for (int o = 1; o < 32; o <<= 1) {
        int v = __shfl_up_sync(0xffffffffu, inc, o);
        if (lane >= o) inc += v;
    }
    if (lane == 31) wsum[w] = inc;
    __syncthreads();
    if (w == 0) {
        int v2 = wsum[lane];
#pragma unroll
        for (int o = 1; o < 32; o <<= 1) {
            int u = __shfl_up_sync(0xffffffffu, v2, o);
            if (lane >= o) v2 += u;
        }
        wsum[lane] = v2;
    }
    __syncthreads();
    int excl = inc - s + (w ? wsum[w - 1] : 0);
#pragma unroll
    for (int i = 0; i < 16; ++i) {
        int idx = base + i;
        if (idx < NNODES) sdeg[idx] = excl + local[i];
    }
    __syncthreads();
    for (int i = t; i < NNODES; i += 1024) g_rowptr[i] = sdeg[i];
    if (t == 1023) g_rowptr[NNODES] = wsum[31];
}

// Atomic-free CSR fill, 4 edges/thread.
__global__ void fill_csr(int E) {
    int e0 = (blockIdx.x * blockDim.x + threadIdx.x) * 4;
    if (e0 + 3 < E) {
        int4 d = *(const int4*)(g_dst + e0);
        int4 q = *(const int4*)(g_seq + e0);
        int4 s = *(const int4*)(g_src + e0);
        int r0 = g_rowptr[d.x];
        int r1 = g_rowptr[d.y];
        int r2 = g_rowptr[d.z];
        int r3 = g_rowptr[d.w];
        g_csr[r0 + q.x] = s.x;
        g_csr[r1 + q.y] = s.y;
        g_csr[r2 + q.z] = s.z;
        g_csr[r3 + q.w] = s.w;
    } else {
        for (int e = e0; e < E; ++e)
            g_csr[g_rowptr[g_dst[e]] + g_seq[e]] = g_src[e];
    }
}

// ---------------------------------------------------------------------------
// Layer-1 gather: reads fp16 x in place at A1[:, 256:512] (row stride KCAT),
// fp32 accumulate, fp16 result into A1[:, 0:256]. Lane owns 8 contiguous cols.
// ---------------------------------------------------------------------------
__global__ void gather_splitA(int Nn) {
    int node = (blockIdx.x * blockDim.x + threadIdx.x) >> 5;
    if (node >= Nn) return;
    int lane = threadIdx.x & 31;
    int r0 = g_rowptr[node];
    int r1 = g_rowptr[node + 1];

    float acc[8];
#pragma unroll
    for (int i = 0; i < 8; ++i) acc[i] = 0.f;

    auto addrow = [&](const uint4 v) {
#pragma unroll
        for (int q = 0; q < 4; ++q) {
            uint32_t word = (q == 0) ? v.x : (q == 1) ? v.y : (q == 2) ? v.z : v.w;
            __half2 h2 = *reinterpret_cast<__half2*>(&word);
            float2 f = __half22float2(h2);
            acc[2 * q]     += f.x;
            acc[2 * q + 1] += f.y;
        }
    };

    const __half* Xsrc = g_A1 + 256;   // fp16 x lives at cols 256:512
    int e = r0;
    for (; e + 1 < r1; e += 2) {
        uint4 v0 = ((const uint4*)(Xsrc + (size_t)g_csr[e]     * KCAT))[lane];
        uint4 v1 = ((const uint4*)(Xsrc + (size_t)g_csr[e + 1] * KCAT))[lane];
        addrow(v0);
        addrow(v1);
    }
    if (e < r1) {
        uint4 v0 = ((const uint4*)(Xsrc + (size_t)g_csr[e] * KCAT))[lane];
        addrow(v0);
    }

    // store: lane owns cols [lane*8, lane*8+8) of A1[:, 0:256)
    uint32_t h[4];
#pragma unroll
    for (int q = 0; q < 4; ++q)
        h[q] = pack2h(acc[2 * q], acc[2 * q + 1]);
    *(uint4*)(g_A1 + (size_t)node * KCAT + lane * 8) = make_uint4(h[0], h[1], h[2], h[3]);
}

// P-gather: out[node] += segsum(fp16 P), F=128. Lane owns 4 cols (uint2 load).
__global__ void gather_P(float* __restrict__ OUT, int Nn) {
    int node = (blockIdx.x * blockDim.x + threadIdx.x) >> 5;
    if (node >= Nn) return;
    int lane = threadIdx.x & 31;
    int r0 = g_rowptr[node];
    int r1 = g_rowptr[node + 1];

    float4 acc = ((const float4*)(OUT + (size_t)node * C_OUT))[lane];
    auto addrow = [&](const uint2 v) {
        __half2 a = *reinterpret_cast<const __half2*>(&v.x);
        __half2 b = *reinterpret_cast<const __half2*>(&v.y);
        float2 fa = __half22float2(a);
        float2 fb = __half22float2(b);
        acc.x += fa.x; acc.y += fa.y; acc.z += fb.x; acc.w += fb.y;
    };
    int e = r0;
    for (; e + 1 < r1; e += 2) {
        uint2 v0 = ((const uint2*)(g_P + (size_t)g_csr[e]     * C_OUT))[lane];
        uint2 v1 = ((const uint2*)(g_P + (size_t)g_csr[e + 1] * C_OUT))[lane];
        addrow(v0);
        addrow(v1);
    }
    if (e < r1) {
        uint2 v0 = ((const uint2*)(g_P + (size_t)g_csr[e] * C_OUT))[lane];
        addrow(v0);
    }
    ((float4*)(OUT + (size_t)node * C_OUT))[lane] = acc;
}

// ---------------------------------------------------------------------------
// HMMA fp16 2-product GEMM.  C = A @ (Bh + Bl).  Tile 128x64, BK=64, 8 warps
// (4m x 2n), warp 32x32.  Stage 32KB (A16 + Bh8 + Bl8), double buffer 64KB,
// 2 CTAs/SM.
// MODE 0 (layer1): C = relu(A@B + bias) -> fp16 H [M][512]
// MODE 1 (layer2): cols <128 -> fp16 P (no bias); cols >=128 -> fp32 OUT (+b2).
// ---------------------------------------------------------------------------
#define STAGE_BYTES 32768
#define GSMEM (2 * STAGE_BYTES)

template <int MODE>
__global__ void __launch_bounds__(256, 2)
gemm_mma(const __half* __restrict__ A,
         const __half* __restrict__ Bh, const __half* __restrict__ Bl,
         const float* __restrict__ bias,       // MODE0: b1
         __half* __restrict__ H,
         __half* __restrict__ P, float* __restrict__ OUT,
         const float* __restrict__ b2, int M) {
    extern __shared__ char smem_raw[];
    const uint32_t sb = smem_u32(smem_raw);
    const int tid  = threadIdx.x;
    const int lane = tid & 31;
    const int w    = tid >> 5;
    const int wm   = w & 3;          // 4 m-blocks of 32
    const int wn   = w >> 2;         // 2 n-blocks of 32
    const int bm   = blockIdx.y * 128;
    const int bn   = blockIdx.x * 64;
    constexpr int T = KCAT / 64;     // 8

    float acc[2][4][4];
#pragma unroll
    for (int i = 0; i < 2; ++i)
#pragma unroll
        for (int j = 0; j < 4; ++j)
#pragma unroll
            for (int c = 0; c < 4; ++c) acc[i][j][c] = 0.f;

    auto load_tile = [&](int t, int s) {
        const int kk = t * 64;
        const uint32_t b0 = sb + s * STAGE_BYTES;
        const uint32_t dA = b0, dBh = b0 + 16384, dBl = b0 + 24576;
#pragma unroll
        for (int i = 0; i < 4; ++i) {                 // A: 1024 chunks (128 rows x 8)
            int idx = tid + i * 256;
            int row = idx >> 3, c = idx & 7;
            int gm = bm + row;
            uint32_t off = swz(row * 128 + c * 16);
            int sz = (gm < M) ? 16 : 0;
            CP_ASYNC16(dA + off, (const char*)(A + (size_t)gm * KCAT + kk + c * 8), sz);
        }
#pragma unroll
        for (int i = 0; i < 2; ++i) {                 // B: 512 chunks (64 n-rows x 8)
            int idx = tid + i * 256;
            int row = idx >> 3, c = idx & 7;
            int gn = bn + row;
            uint32_t off = swz(row * 128 + c * 16);
            CP_ASYNC16(dBh + off, (const char*)(Bh + (size_t)gn * KCAT + kk + c * 8), 16);
            CP_ASYNC16(dBl + off, (const char*)(Bl + (size_t)gn * KCAT + kk + c * 8), 16);
        }
    };

    const int lr16 = lane & 15;
    const int lc8  = (lane >> 4) * 8;

    auto compute = [&](int s) {
        const uint32_t b0 = sb + s * STAGE_BYTES;
        const uint32_t aA = b0, bH = b0 + 16384, bL = b0 + 24576;
#pragma unroll
        for (int ks = 0; ks < 4; ++ks) {
            const int k0 = ks * 16;
            uint32_t ah[2][4];
#pragma unroll
            for (int i = 0; i < 2; ++i) {
                uint32_t off = swz((uint32_t)((wm * 32 + i * 16 + lr16) * 128 + (k0 + lc8) * 2));
                LDSM_X4(ah[i][0], ah[i][1], ah[i][2], ah[i][3], aA + off);
            }
            uint32_t bh[4][2], bl[4][2];
#pragma unroll
            for (int jp = 0; jp < 2; ++jp) {
                uint32_t off = swz((uint32_t)((wn * 32 + jp * 16 + lr16) * 128 + (k0 + lc8) * 2));
                uint32_t q0, q1, q2, q3;
                LDSM_X4(q0, q1, q2, q3, bH + off);
                bh[2 * jp][0] = q0; bh[2 * jp][1] = q2;
                bh[2 * jp + 1][0] = q1; bh[2 * jp + 1][1] = q3;
                LDSM_X4(q0, q1, q2, q3, bL + off);
                bl[2 * jp][0] = q0; bl[2 * jp][1] = q2;
                bl[2 * jp + 1][0] = q1; bl[2 * jp + 1][1] = q3;
            }
#pragma unroll
            for (int i = 0; i < 2; ++i)
#pragma unroll
                for (int j = 0; j < 4; ++j) {
                    mma16816(acc[i][j], ah[i][0], ah[i][1], ah[i][2], ah[i][3],
                             bh[j][0], bh[j][1]);
                    mma16816(acc[i][j], ah[i][0], ah[i][1], ah[i][2], ah[i][3],
                             bl[j][0], bl[j][1]);
                }
        }
    };

    load_tile(0, 0);
    CP_COMMIT();
    for (int t = 0; t < T; ++t) {
        const int s = t & 1;
        CP_WAIT0();
        __syncthreads();
        if (t + 1 < T) { load_tile(t + 1, s ^ 1); CP_COMMIT(); }
        compute(s);
        __syncthreads();
    }

    // ---- epilogue ----
#pragma unroll
    for (int i = 0; i < 2; ++i) {
        const int m0 = bm + wm * 32 + i * 16 + (lane >> 2);
#pragma unroll
        for (int j = 0; j < 4; ++j) {
            const int n = bn + wn * 32 + j * 8 + (lane & 3) * 2;
            if (MODE == 0) {
                float2 bb = *(const float2*)(bias + n);
                float v0 = fmaxf(acc[i][j][0] + bb.x, 0.f);
                float v1 = fmaxf(acc[i][j][1] + bb.y, 0.f);
                float v2 = fmaxf(acc[i][j][2] + bb.x, 0.f);
                float v3 = fmaxf(acc[i][j][3] + bb.y, 0.f);
                if (m0 < M)
                    *(uint32_t*)(H + (size_t)m0 * KCAT + n) = pack2h(v0, v1);
                if (m0 + 8 < M)
                    *(uint32_t*)(H + (size_t)(m0 + 8) * KCAT + n) = pack2h(v2, v3);
            } else {
                const int cn = (n < 128) ? n : (n - 128);
                if (n < 128) {          // P, fp16, no bias
                    if (m0 < M)
                        *(uint32_t*)(P + (size_t)m0 * C_OUT + cn) =
                            pack2h(acc[i][j][0], acc[i][j][1]);
                    if (m0 + 8 < M)
                        *(uint32_t*)(P + (size_t)(m0 + 8) * C_OUT + cn) =
                            pack2h(acc[i][j][2], acc[i][j][3]);
                } else {                // OUT, fp32, +b2
                    float2 bb = *(const float2*)(b2 + cn);
                    if (m0 < M)
                        *(float2*)(OUT + (size_t)m0 * C_OUT + cn) =
                            make_float2(acc[i][j][0] + bb.x, acc[i][j][1] + bb.y);
                    if (m0 + 8 < M)
                        *(float2*)(OUT + (size_t)(m0 + 8) * C_OUT + cn) =
                            make_float2(acc[i][j][2] + bb.x, acc[i][j][3] + bb.y);
                }
            }
        }
    }
}

// ---------------------------------------------------------------------------
extern "C" void kernel_launch(void* const* d_in, const int* in_sizes, int n_in,
                              void* d_out, int out_size) {
    const float* x   = (const float*)d_in[0];
    const void*  ei  = d_in[1];
    const float* W1l = (const float*)d_in[2];
    const float* b1  = (const float*)d_in[3];
    const float* W1r = (const float*)d_in[4];
    const float* W2l = (const float*)d_in[5];
    const float* b2  = (const float*)d_in[6];
    const float* W2r = (const float*)d_in[7];
    float*       out = (float*)d_out;

    const int M = in_sizes[0] / F_IN;    // 10000
    const int E = in_sizes[1] / 2;       // 320000

    __half *P, *A1, *H, *B1h, *B1l, *B2h, *B2l;
    cudaGetSymbolAddress((void**)&P,   g_P);
    cudaGetSymbolAddress((void**)&A1,  g_A1);
    cudaGetSymbolAddress((void**)&H,   g_H);
    cudaGetSymbolAddress((void**)&B1h, g_B1h);
    cudaGetSymbolAddress((void**)&B1l, g_B1l);
    cudaGetSymbolAddress((void**)&B2h, g_B2h);
    cudaGetSymbolAddress((void**)&B2l, g_B2l);

    static int smem_set = 0;
    if (!smem_set) {
        cudaFuncSetAttribute(gemm_mma<0>, cudaFuncAttributeMaxDynamicSharedMemorySize, GSMEM);
        cudaFuncSetAttribute(gemm_mma<1>, cudaFuncAttributeMaxDynamicSharedMemorySize, GSMEM);
        smem_set = 1;
    }

    // ---- front kernel: edge decode + hist concurrent with weight/x prep ----
    const int eb = (E + 511) / 512;
    const int xb = (M * 128 + 255) / 256;
    convert_and_prep<<<eb + 96 + xb, 256>>>(ei, x, W1l, W1r, W2l, W2r, eb, E, M);

    // ---- CSR: scan (+deg reset) then atomic-free fill ----
    build_rowptr<<<1, 1024>>>();
    fill_csr<<<(E / 4 + 255) / 256 + 1, 256>>>(E);

    // ---- Layer 1: A1[:,0:256] = fp16(segsum(fp16 x in A1[:,256:512]));
    //      h(fp16) = relu(A1 @ [W1l;W1r] + b1) ----
    gather_splitA<<<(M * 32 + 255) / 256, 256>>>(M);
    {
        dim3 grid(HID / 64, (M + 127) / 128);   // (8, 79)
        gemm_mma<0><<<grid, 256, GSMEM>>>(A1, B1h, B1l, b1,
                                          H, nullptr, nullptr, nullptr, M);
    }

    // ---- Layer 2 (linearity reorder): [P|out] = h @ [W2l|W2r] (+b2 on out);
    //      out += segsum(P) ----
    {
        dim3 grid(2 * C_OUT / 64, (M + 127) / 128);  // (4, 79)
        gemm_mma<1><<<grid, 256, GSMEM>>>(H, B2h, B2l, nullptr,
                                          nullptr, P, out, b2, M);
    }
    gather_P<<<(M * 32 + 255) / 256, 256>>>(out, M);
}

// round 17
// speedup vs baseline: 1.6179x; 1.0170x over previous
#include <cuda_runtime.h>
#include <cuda_fp16.h>
#include <cstdint>

#define NNODES 10000
#define F_IN   256
#define HID    512
#define C_OUT  128
#define NEDGES 320000
#define KCAT   512            // K for both fused GEMMs

// ---------------------------------------------------------------------------
// Scratch (allocation-free rule: __device__ globals)
// g_deg: zero-initialized at load; re-zeroed by build_rowptr after each
// consume -> every invocation (incl. graph replays) sees zeros.
// Precision: A operands single fp16 (2^-11 random-sign rounding); B operands
// exact fp16 hi+lo split (residue 2^-22). D = A*Bh + A*Bl (2 MMA products).
// Gathers accumulate via depth-2 fp16 pairwise tree then fp32 (adds ~2^-11
// random-sign per level; measured class).
// ---------------------------------------------------------------------------
__device__ __align__(1024) __half g_P  [NNODES * C_OUT];       // h @ W2l fp16
__device__ __align__(1024) __half g_A1 [NNODES * KCAT];        // [agg1|x] fp16 (cols 256:512 = fp16 x, also the gather source)
__device__ __align__(1024) __half g_H  [NNODES * KCAT];        // h fp16
__device__ __align__(1024) __half g_B1h[HID * KCAT];           // [W1l;W1r]^T hi [512][512]
__device__ __align__(1024) __half g_B1l[HID * KCAT];
__device__ __align__(1024) __half g_B2h[(2 * C_OUT) * KCAT];   // [W2l|W2r]^T hi [256][512]
__device__ __align__(1024) __half g_B2l[(2 * C_OUT) * KCAT];
__device__ int g_src[NEDGES];
__device__ int g_dst[NEDGES];
__device__ int g_seq[NEDGES];
__device__ int g_deg[NNODES];
__device__ int g_rowptr[NNODES + 1];
__device__ int g_csr[NEDGES];

// ---------------------------------------------------------------------------
// PTX helpers (plain sm_80+ PTX; NO sm_103a-only features — harness targets sm_103)
// ---------------------------------------------------------------------------
__device__ __forceinline__ uint32_t smem_u32(const void* p) {
    uint32_t a;
    asm("{ .reg .u64 t; cvta.to.shared.u64 t, %1; cvt.u32.u64 %0, t; }"
        : "=r"(a) : "l"(p));
    return a;
}
#define CP_ASYNC16(dst, src, sz) \
    asm volatile("cp.async.cg.shared.global [%0], [%1], 16, %2;" \
                 :: "r"(dst), "l"(src), "r"(sz) : "memory")
#define CP_COMMIT() asm volatile("cp.async.commit_group;" ::: "memory")
#define CP_WAIT0()  asm volatile("cp.async.wait_group 0;" ::: "memory")
#define LDSM_X4(r0, r1, r2, r3, addr) \
    asm volatile("ldmatrix.sync.aligned.m8n8.x4.shared.b16 {%0,%1,%2,%3}, [%4];" \
                 : "=r"(r0), "=r"(r1), "=r"(r2), "=r"(r3) : "r"(addr))

__device__ __forceinline__ void mma16816(float c[4],
                                         uint32_t a0, uint32_t a1, uint32_t a2, uint32_t a3,
                                         uint32_t b0, uint32_t b1) {
    asm volatile(
        "mma.sync.aligned.m16n8k16.row.col.f32.f16.f16.f32 "
        "{%0,%1,%2,%3}, {%4,%5,%6,%7}, {%8,%9}, {%0,%1,%2,%3};"
        : "+f"(c[0]), "+f"(c[1]), "+f"(c[2]), "+f"(c[3])
        : "r"(a0), "r"(a1), "r"(a2), "r"(a3), "r"(b0), "r"(b1));
}

__device__ __forceinline__ uint32_t swz(uint32_t off) {   // SW128-style XOR
    return off ^ ((off >> 3) & 0x70);
}

// fp32 -> fp16 hi/lo exact split (residue ~2^-22), packed as half2 words.
__device__ __forceinline__ void split2h(float a, float b, uint32_t& h2o, uint32_t& l2o) {
    __half2 hv, lv;
    hv.x = __float2half(a);
    hv.y = __float2half(b);
    lv.x = __float2half(a - __half2float(hv.x));
    lv.y = __float2half(b - __half2float(hv.y));
    h2o = *reinterpret_cast<uint32_t*>(&hv);
    l2o = *reinterpret_cast<uint32_t*>(&lv);
}

__device__ __forceinline__ uint32_t pack2h(float a, float b) {
    __half2 hv;
    hv.x = __float2half(a);
    hv.y = __float2half(b);
    return *reinterpret_cast<uint32_t*>(&hv);
}

__device__ __forceinline__ __half2 h2of(uint32_t w) {
    return *reinterpret_cast<__half2*>(&w);
}

__device__ __forceinline__ int clampi(long long v, int hi) {
    int r = (int)v;
    if (v < 0) r = 0;
    if (v >= hi) r = hi - 1;
    return r;
}

// ---------------------------------------------------------------------------
// Front kernel: grid-partitioned independent work running concurrently.
//   blocks [0, eb):      edge decode (2 edges/thread) + degree hist + seq
//   blocks [eb, eb+96):  weight transpose + fp16 split (64x64 smem tiles)
//   blocks [eb+96, ...): x -> fp16 into A1[:, 256:512] (doubles as gather src)
// ---------------------------------------------------------------------------
__global__ void convert_and_prep(const void* __restrict__ ei,
                                 const float* __restrict__ x,
                                 const float* __restrict__ W1l, const float* __restrict__ W1r,
                                 const float* __restrict__ W2l, const float* __restrict__ W2r,
                                 int eb, int E, int M) {
    const int b = blockIdx.x;
    const int tid = threadIdx.x;

    if (b < eb) {
        __shared__ int s_any;
        if (tid == 0) s_any = 0;
        __syncthreads();
        const int* p32 = (const int*)ei;
        int n_check = (2 * E < 2048) ? 2 * E : 2048;
        int any = 0;
        for (int i = 2 * tid + 1; i < n_check; i += 512) any |= p32[i];
        if (any) atomicOr(&s_any, 1);
        __syncthreads();
        const int is32 = s_any;

        int e0 = (b * 256 + tid) * 2;
        if (e0 + 1 < E) {
            long long s0, s1, d0, d1;
            if (is32) {
                int2 sp = *(const int2*)(p32 + e0);
                int2 dp = *(const int2*)(p32 + E + e0);
                s0 = sp.x; s1 = sp.y; d0 = dp.x; d1 = dp.y;
            } else {
                const long long* p64 = (const long long*)ei;
                longlong2 sp = *(const longlong2*)(p64 + e0);
                longlong2 dp = *(const longlong2*)(p64 + E + e0);
                s0 = sp.x; s1 = sp.y; d0 = dp.x; d1 = dp.y;
            }
            int si0 = clampi(s0, NNODES), si1 = clampi(s1, NNODES);
            int di0 = clampi(d0, NNODES), di1 = clampi(d1, NNODES);
            *(int2*)(g_src + e0) = make_int2(si0, si1);
            *(int2*)(g_dst + e0) = make_int2(di0, di1);
            int q0 = atomicAdd(&g_deg[di0], 1);
            int q1 = atomicAdd(&g_deg[di1], 1);
            *(int2*)(g_seq + e0) = make_int2(q0, q1);
        }
        return;
    }

    if (b < eb + 96) {
        const int wb = b - eb;
        __shared__ float tile[64][65];
        const float* W;
        __half *Dh, *Dl;
        int ldw, roff, coff, nt, kt;
        if (wb < 64) {                 // layer-1 weights -> g_B1 [512][512]
            nt = (wb & 7) * 64; kt = (wb >> 3) * 64;
            if (kt < 256) { W = W1l; roff = kt; } else { W = W1r; roff = kt - 256; }
            ldw = 512; coff = nt;
            Dh = g_B1h; Dl = g_B1l;
        } else {                       // layer-2 weights -> g_B2 [256][512]
            int t = wb - 64;
            nt = (t & 3) * 64; kt = (t >> 2) * 64;
            if (nt < 128) { W = W2l; coff = nt; } else { W = W2r; coff = nt - 128; }
            ldw = 128; roff = kt;
            Dh = g_B2h; Dl = g_B2l;
        }
#pragma unroll
        for (int pass = 0; pass < 16; ++pass) {
            int r = pass * 4 + (tid >> 6);
            int c = tid & 63;
            tile[c][r] = W[(size_t)(roff + r) * ldw + coff + c];
        }
        __syncthreads();
#pragma unroll
        for (int pass = 0; pass < 8; ++pass) {
            int n0 = pass * 8 + (tid >> 5);
            int k0 = (tid & 31) * 2;
            uint32_t h2, l2;
            split2h(tile[n0][k0], tile[n0][k0 + 1], h2, l2);
            size_t off = (size_t)(nt + n0) * KCAT + kt + k0;
            *(uint32_t*)(Dh + off) = h2;
            *(uint32_t*)(Dl + off) = l2;
        }
        return;
    }

    // ---- x -> fp16 into A1[:, 256:512] ----
    int p = (b - eb - 96) * 256 + tid;
    if (p < M * 128) {
        int m = p >> 7;
        int c2 = (p & 127) * 2;
        *(uint32_t*)(g_A1 + (size_t)m * KCAT + 256 + c2) =
            pack2h(x[m * 256 + c2], x[m * 256 + c2 + 1]);
    }
}

// ---------------------------------------------------------------------------
// Exclusive scan of g_deg -> g_rowptr (coalesced via smem staging).
// Re-zeroes g_deg for the next invocation.
// ---------------------------------------------------------------------------
__global__ void build_rowptr() {
    __shared__ int sdeg[NNODES];      // 40 KB
    __shared__ int wsum[32];
    const int t = threadIdx.x;
    const int lane = t & 31, w = t >> 5;

    for (int i = t; i < NNODES; i += 1024) {
        sdeg[i] = g_deg[i];
        g_deg[i] = 0;
    }
    __syncthreads();

    const int base = t * 16;
    int local[16];
    int s = 0;
#pragma unroll
    for (int i = 0; i < 16; ++i) {
        int idx = base + i;
        int v = (idx < NNODES) ? sdeg[idx] : 0;
        local[i] = s; s += v;
    }
    int inc = s;
#pragma unroll
    for (int o = 1; o < 32; o <<= 1) {
        int v = __shfl_up_sync(0xffffffffu, inc, o);
        if (lane >= o) inc += v;
    }
    if (lane == 31) wsum[w] = inc;
    __syncthreads();
    if (w == 0) {
        int v2 = wsum[lane];
#pragma unroll
        for (int o = 1; o < 32; o <<= 1) {
            int u = __shfl_up_sync(0xffffffffu, v2, o);
            if (lane >= o) v2 += u;
        }
        wsum[lane] = v2;
    }
    __syncthreads();
    int excl = inc - s + (w ? wsum[w - 1] : 0);
#pragma unroll
    for (int i = 0; i < 16; ++i) {
        int idx = base + i;
        if (idx < NNODES) sdeg[idx] = excl + local[i];
    }
    __syncthreads();
    for (int i = t; i < NNODES; i += 1024) g_rowptr[i] = sdeg[i];
    if (t == 1023) g_rowptr[NNODES] = wsum[31];
}

// Atomic-free CSR fill, 4 edges/thread.
__global__ void fill_csr(int E) {
    int e0 = (blockIdx.x * blockDim.x + threadIdx.x) * 4;
    if (e0 + 3 < E) {
        int4 d = *(const int4*)(g_dst + e0);
        int4 q = *(const int4*)(g_seq + e0);
        int4 s = *(const int4*)(g_src + e0);
        int r0 = g_rowptr[d.x];
        int r1 = g_rowptr[d.y];
        int r2 = g_rowptr[d.z];
        int r3 = g_rowptr[d.w];
        g_csr[r0 + q.x] = s.x;
        g_csr[r1 + q.y] = s.y;
        g_csr[r2 + q.z] = s.z;
        g_csr[r3 + q.w] = s.w;
    } else {
        for (int e = e0; e < E; ++e)
            g_csr[g_rowptr[g_dst[e]] + g_seq[e]] = g_src[e];
    }
}

// ---------------------------------------------------------------------------
// Layer-1 gather: reads fp16 x in place at A1[:, 256:512] (row stride KCAT),
// depth-2 fp16 pairwise tree (HADD2) then fp32 accumulate; fp16 result into
// A1[:, 0:256]. Lane owns 8 contiguous cols (one uint4 per edge).
// ---------------------------------------------------------------------------
__global__ void gather_splitA(int Nn) {
    int node = (blockIdx.x * blockDim.x + threadIdx.x) >> 5;
    if (node >= Nn) return;
    int lane = threadIdx.x & 31;
    int r0 = g_rowptr[node];
    int r1 = g_rowptr[node + 1];

    float acc[8];
#pragma unroll
    for (int i = 0; i < 8; ++i) acc[i] = 0.f;

    auto acc_h2 = [&](int q, __half2 h) {
        float2 f = __half22float2(h);
        acc[2 * q]     += f.x;
        acc[2 * q + 1] += f.y;
    };

    const __half* Xsrc = g_A1 + 256;   // fp16 x lives at cols 256:512
    int e = r0;
    for (; e + 3 < r1; e += 4) {
        uint4 v0 = ((const uint4*)(Xsrc + (size_t)g_csr[e]     * KCAT))[lane];
        uint4 v1 = ((const uint4*)(Xsrc + (size_t)g_csr[e + 1] * KCAT))[lane];
        uint4 v2 = ((const uint4*)(Xsrc + (size_t)g_csr[e + 2] * KCAT))[lane];
        uint4 v3 = ((const uint4*)(Xsrc + (size_t)g_csr[e + 3] * KCAT))[lane];
        // depth-2 fp16 tree per word
        acc_h2(0, __hadd2(__hadd2(h2of(v0.x), h2of(v1.x)), __hadd2(h2of(v2.x), h2of(v3.x))));
        acc_h2(1, __hadd2(__hadd2(h2of(v0.y), h2of(v1.y)), __hadd2(h2of(v2.y), h2of(v3.y))));
        acc_h2(2, __hadd2(__hadd2(h2of(v0.z), h2of(v1.z)), __hadd2(h2of(v2.z), h2of(v3.z))));
        acc_h2(3, __hadd2(__hadd2(h2of(v0.w), h2of(v1.w)), __hadd2(h2of(v2.w), h2of(v3.w))));
    }
    for (; e + 1 < r1; e += 2) {
        uint4 v0 = ((const uint4*)(Xsrc + (size_t)g_csr[e]     * KCAT))[lane];
        uint4 v1 = ((const uint4*)(Xsrc + (size_t)g_csr[e + 1] * KCAT))[lane];
        acc_h2(0, __hadd2(h2of(v0.x), h2of(v1.x)));
        acc_h2(1, __hadd2(h2of(v0.y), h2of(v1.y)));
        acc_h2(2, __hadd2(h2of(v0.z), h2of(v1.z)));
        acc_h2(3, __hadd2(h2of(v0.w), h2of(v1.w)));
    }
    if (e < r1) {
        uint4 v0 = ((const uint4*)(Xsrc + (size_t)g_csr[e] * KCAT))[lane];
        acc_h2(0, h2of(v0.x));
        acc_h2(1, h2of(v0.y));
        acc_h2(2, h2of(v0.z));
        acc_h2(3, h2of(v0.w));
    }

    // store: lane owns cols [lane*8, lane*8+8) of A1[:, 0:256)
    uint32_t h[4];
#pragma unroll
    for (int q = 0; q < 4; ++q)
        h[q] = pack2h(acc[2 * q], acc[2 * q + 1]);
    *(uint4*)(g_A1 + (size_t)node * KCAT + lane * 8) = make_uint4(h[0], h[1], h[2], h[3]);
}

// P-gather: out[node] += segsum(fp16 P), F=128. Lane owns 4 cols (uint2),
// fp16 pair-add then fp32 accumulate.
__global__ void gather_P(float* __restrict__ OUT, int Nn) {
    int node = (blockIdx.x * blockDim.x + threadIdx.x) >> 5;
    if (node >= Nn) return;
    int lane = threadIdx.x & 31;
    int r0 = g_rowptr[node];
    int r1 = g_rowptr[node + 1];

    float4 acc = ((const float4*)(OUT + (size_t)node * C_OUT))[lane];
    auto acc_h2 = [&](__half2 a, __half2 b) {
        float2 fa = __half22float2(a);
        float2 fb = __half22float2(b);
        acc.x += fa.x; acc.y += fa.y; acc.z += fb.x; acc.w += fb.y;
    };
    int e = r0;
    for (; e + 3 < r1; e += 4) {
        uint2 v0 = ((const uint2*)(g_P + (size_t)g_csr[e]     * C_OUT))[lane];
        uint2 v1 = ((const uint2*)(g_P + (size_t)g_csr[e + 1] * C_OUT))[lane];
        uint2 v2 = ((const uint2*)(g_P + (size_t)g_csr[e + 2] * C_OUT))[lane];
        uint2 v3 = ((const uint2*)(g_P + (size_t)g_csr[e + 3] * C_OUT))[lane];
        acc_h2(__hadd2(__hadd2(h2of(v0.x), h2of(v1.x)), __hadd2(h2of(v2.x), h2of(v3.x))),
               __hadd2(__hadd2(h2of(v0.y), h2of(v1.y)), __hadd2(h2of(v2.y), h2of(v3.y))));
    }
    for (; e + 1 < r1; e += 2) {
        uint2 v0 = ((const uint2*)(g_P + (size_t)g_csr[e]     * C_OUT))[lane];
        uint2 v1 = ((const uint2*)(g_P + (size_t)g_csr[e + 1] * C_OUT))[lane];
        acc_h2(__hadd2(h2of(v0.x), h2of(v1.x)), __hadd2(h2of(v0.y), h2of(v1.y)));
    }
    if (e < r1) {
        uint2 v0 = ((const uint2*)(g_P + (size_t)g_csr[e] * C_OUT))[lane];
        acc_h2(h2of(v0.x), h2of(v0.y));
    }
    ((float4*)(OUT + (size_t)node * C_OUT))[lane] = acc;
}

// ---------------------------------------------------------------------------
// HMMA fp16 2-product GEMM.  C = A @ (Bh + Bl).  Tile 128x64, BK=64, 8 warps
// (4m x 2n), warp 32x32.  Stage 32KB, double buffer 64KB, 2 CTAs/SM.
// MODE 0 (layer1): C = relu(A@B + bias) -> fp16 H [M][512]
// MODE 1 (layer2): cols <128 -> fp16 P (no bias); cols >=128 -> fp32 OUT (+b2).
// ---------------------------------------------------------------------------
#define STAGE_BYTES 32768
#define GSMEM (2 * STAGE_BYTES)

template <int MODE>
__global__ void __launch_bounds__(256, 2)
gemm_mma(const __half* __restrict__ A,
         const __half* __restrict__ Bh, const __half* __restrict__ Bl,
         const float* __restrict__ bias,       // MODE0: b1
         __half* __restrict__ H,
         __half* __restrict__ P, float* __restrict__ OUT,
         const float* __restrict__ b2, int M) {
    extern __shared__ char smem_raw[];
    const uint32_t sb = smem_u32(smem_raw);
    const int tid  = threadIdx.x;
    const int lane = tid & 31;
    const int w    = tid >> 5;
    const int wm   = w & 3;          // 4 m-blocks of 32
    const int wn   = w >> 2;         // 2 n-blocks of 32
    const int bm   = blockIdx.y * 128;
    const int bn   = blockIdx.x * 64;
    constexpr int T = KCAT / 64;     // 8

    float acc[2][4][4];
#pragma unroll
    for (int i = 0; i < 2; ++i)
#pragma unroll
        for (int j = 0; j < 4; ++j)
#pragma unroll
            for (int c = 0; c < 4; ++c) acc[i][j][c] = 0.f;

    auto load_tile = [&](int t, int s) {
        const int kk = t * 64;
        const uint32_t b0 = sb + s * STAGE_BYTES;
        const uint32_t dA = b0, dBh = b0 + 16384, dBl = b0 + 24576;
#pragma unroll
        for (int i = 0; i < 4; ++i) {                 // A: 1024 chunks (128 rows x 8)
            int idx = tid + i * 256;
            int row = idx >> 3, c = idx & 7;
            int gm = bm + row;
            uint32_t off = swz(row * 128 + c * 16);
            int sz = (gm < M) ? 16 : 0;
            CP_ASYNC16(dA + off, (const char*)(A + (size_t)gm * KCAT + kk + c * 8), sz);
        }
#pragma unroll
        for (int i = 0; i < 2; ++i) {                 // B: 512 chunks (64 n-rows x 8)
            int idx = tid + i * 256;
            int row = idx >> 3, c = idx & 7;
            int gn = bn + row;
            uint32_t off = swz(row * 128 + c * 16);
            CP_ASYNC16(dBh + off, (const char*)(Bh + (size_t)gn * KCAT + kk + c * 8), 16);
            CP_ASYNC16(dBl + off, (const char*)(Bl + (size_t)gn * KCAT + kk + c * 8), 16);
        }
    };

    const int lr16 = lane & 15;
    const int lc8  = (lane >> 4) * 8;

    auto compute = [&](int s) {
        const uint32_t b0 = sb + s * STAGE_BYTES;
        const uint32_t aA = b0, bH = b0 + 16384, bL = b0 + 24576;
#pragma unroll
        for (int ks = 0; ks < 4; ++ks) {
            const int k0 = ks * 16;
            uint32_t ah[2][4];
#pragma unroll
            for (int i = 0; i < 2; ++i) {
                uint32_t off = swz((uint32_t)((wm * 32 + i * 16 + lr16) * 128 + (k0 + lc8) * 2));
                LDSM_X4(ah[i][0], ah[i][1], ah[i][2], ah[i][3], aA + off);
            }
            uint32_t bh[4][2], bl[4][2];
#pragma unroll
            for (int jp = 0; jp < 2; ++jp) {
                uint32_t off = swz((uint32_t)((wn * 32 + jp * 16 + lr16) * 128 + (k0 + lc8) * 2));
                uint32_t q0, q1, q2, q3;
                LDSM_X4(q0, q1, q2, q3, bH + off);
                bh[2 * jp][0] = q0; bh[2 * jp][1] = q2;
                bh[2 * jp + 1][0] = q1; bh[2 * jp + 1][1] = q3;
                LDSM_X4(q0, q1, q2, q3, bL + off);
                bl[2 * jp][0] = q0; bl[2 * jp][1] = q2;
                bl[2 * jp + 1][0] = q1; bl[2 * jp + 1][1] = q3;
            }
#pragma unroll
            for (int i = 0; i < 2; ++i)
#pragma unroll
                for (int j = 0; j < 4; ++j) {
                    mma16816(acc[i][j], ah[i][0], ah[i][1], ah[i][2], ah[i][3],
                             bh[j][0], bh[j][1]);
                    mma16816(acc[i][j], ah[i][0], ah[i][1], ah[i][2], ah[i][3],
                             bl[j][0], bl[j][1]);
                }
        }
    };

    load_tile(0, 0);
    CP_COMMIT();
    for (int t = 0; t < T; ++t) {
        const int s = t & 1;
        CP_WAIT0();
        __syncthreads();
        if (t + 1 < T) { load_tile(t + 1, s ^ 1); CP_COMMIT(); }
        compute(s);
        __syncthreads();
    }

    // ---- epilogue ----
#pragma unroll
    for (int i = 0; i < 2; ++i) {
        const int m0 = bm + wm * 32 + i * 16 + (lane >> 2);
#pragma unroll
        for (int j = 0; j < 4; ++j) {
            const int n = bn + wn * 32 + j * 8 + (lane & 3) * 2;
            if (MODE == 0) {
                float2 bb = *(const float2*)(bias + n);
                float v0 = fmaxf(acc[i][j][0] + bb.x, 0.f);
                float v1 = fmaxf(acc[i][j][1] + bb.y, 0.f);
                float v2 = fmaxf(acc[i][j][2] + bb.x, 0.f);
                float v3 = fmaxf(acc[i][j][3] + bb.y, 0.f);
                if (m0 < M)
                    *(uint32_t*)(H + (size_t)m0 * KCAT + n) = pack2h(v0, v1);
                if (m0 + 8 < M)
                    *(uint32_t*)(H + (size_t)(m0 + 8) * KCAT + n) = pack2h(v2, v3);
            } else {
                const int cn = (n < 128) ? n : (n - 128);
                if (n < 128) {          // P, fp16, no bias
                    if (m0 < M)
                        *(uint32_t*)(P + (size_t)m0 * C_OUT + cn) =
                            pack2h(acc[i][j][0], acc[i][j][1]);
                    if (m0 + 8 < M)
                        *(uint32_t*)(P + (size_t)(m0 + 8) * C_OUT + cn) =
                            pack2h(acc[i][j][2], acc[i][j][3]);
                } else {                // OUT, fp32, +b2
                    float2 bb = *(const float2*)(b2 + cn);
                    if (m0 < M)
                        *(float2*)(OUT + (size_t)m0 * C_OUT + cn) =
                            make_float2(acc[i][j][0] + bb.x, acc[i][j][1] + bb.y);
                    if (m0 + 8 < M)
                        *(float2*)(OUT + (size_t)(m0 + 8) * C_OUT + cn) =
                            make_float2(acc[i][j][2] + bb.x, acc[i][j][3] + bb.y);
                }
            }
        }
    }
}

// ---------------------------------------------------------------------------
extern "C" void kernel_launch(void* const* d_in, const int* in_sizes, int n_in,
                              void* d_out, int out_size) {
    const float* x   = (const float*)d_in[0];
    const void*  ei  = d_in[1];
    const float* W1l = (const float*)d_in[2];
    const float* b1  = (const float*)d_in[3];
    const float* W1r = (const float*)d_in[4];
    const float* W2l = (const float*)d_in[5];
    const float* b2  = (const float*)d_in[6];
    const float* W2r = (const float*)d_in[7];
    float*       out = (float*)d_out;

    const int M = in_sizes[0] / F_IN;    // 10000
    const int E = in_sizes[1] / 2;       // 320000

    __half *P, *A1, *H, *B1h, *B1l, *B2h, *B2l;
    cudaGetSymbolAddress((void**)&P,   g_P);
    cudaGetSymbolAddress((void**)&A1,  g_A1);
    cudaGetSymbolAddress((void**)&H,   g_H);
    cudaGetSymbolAddress((void**)&B1h, g_B1h);
    cudaGetSymbolAddress((void**)&B1l, g_B1l);
    cudaGetSymbolAddress((void**)&B2h, g_B2h);
    cudaGetSymbolAddress((void**)&B2l, g_B2l);

    static int smem_set = 0;
    if (!smem_set) {
        cudaFuncSetAttribute(gemm_mma<0>, cudaFuncAttributeMaxDynamicSharedMemorySize, GSMEM);
        cudaFuncSetAttribute(gemm_mma<1>, cudaFuncAttributeMaxDynamicSharedMemorySize, GSMEM);
        smem_set = 1;
    }

    // ---- front kernel: edge decode + hist concurrent with weight/x prep ----
    const int eb = (E + 511) / 512;
    const int xb = (M * 128 + 255) / 256;
    convert_and_prep<<<eb + 96 + xb, 256>>>(ei, x, W1l, W1r, W2l, W2r, eb, E, M);

    // ---- CSR: scan (+deg reset) then atomic-free fill ----
    build_rowptr<<<1, 1024>>>();
    fill_csr<<<(E / 4 + 255) / 256 + 1, 256>>>(E);

    // ---- Layer 1: A1[:,0:256] = fp16(segsum(fp16 x in A1[:,256:512]));
    //      h(fp16) = relu(A1 @ [W1l;W1r] + b1) ----
    gather_splitA<<<(M * 32 + 255) / 256, 256>>>(M);
    {
        dim3 grid(HID / 64, (M + 127) / 128);   // (8, 79)
        gemm_mma<0><<<grid, 256, GSMEM>>>(A1, B1h, B1l, b1,
                                          H, nullptr, nullptr, nullptr, M);
    }

    // ---- Layer 2 (linearity reorder): [P|out] = h @ [W2l|W2r] (+b2 on out);
    //      out += segsum(P) ----
    {
        dim3 grid(2 * C_OUT / 64, (M + 127) / 128);  // (4, 79)
        gemm_mma<1><<<grid, 256, GSMEM>>>(H, B2h, B2l, nullptr,
                                          nullptr, P, out, b2, M);
    }
    gather_P<<<(M * 32 + 255) / 256, 256>>>(out, M);
}